// round 1
// baseline (speedup 1.0000x reference)
#include <cuda_runtime.h>
#include <math.h>

#define NN   50000      // nodes
#define NE   800000     // edges
#define NFD  128        // node feature size
#define EFD  64         // edge feature size
#define LL   256        // layer size (mlp1 out)
#define DD1  193        // mlp1 input dim
#define DD2  385        // mlp2 dim
#define BNEPS 1e-5f

// ---------------- scratch (static device globals; no runtime allocation) ----
__device__ float g_Y1[(size_t)NE * LL];     // edge MLP pre-BN output  (819 MB)
__device__ float g_Y2[(size_t)NN * DD2];    // node MLP pre-BN output  (77 MB)
__device__ float g_ssum[(size_t)NN * LL];   // scatter sum / agg       (51 MB)
__device__ int   g_cnt[NN];
__device__ float g_sum1[LL],  g_sumsq1[LL],  g_scale1[LL],  g_shift1[LL];
__device__ float g_sum2[DD2], g_sumsq2[DD2], g_scale2[DD2], g_shift2[DD2];

// ---------------- generic tiled SGEMM: C[M,Nc] = A[M,K] @ B[K,Nc] + bias ----
// A is produced on the fly per MODE:
//   MODE 0: edge rows  = [x[erow[m]], batch[erow[m]], eattr[m]]
//   MODE 1: node rows  = [x[m], batch[m], agg[m]]
//   MODE 2: relu(bn(Y2[m]))  (scale/shift precomputed)
template<int MODE>
__global__ void gemm_kernel(int M, int Nc, int K,
    const float* __restrict__ B, const float* __restrict__ bias,
    float* __restrict__ C,
    const float* __restrict__ x, const int* __restrict__ erow,
    const float* __restrict__ eattr, const int* __restrict__ batch,
    const float* __restrict__ agg,
    const float* __restrict__ Y2,
    const float* __restrict__ scale, const float* __restrict__ shift,
    int relu_out)
{
    __shared__ float As[16][64];   // k-major (transposed) for float4 reads
    __shared__ float Bs[16][64];

    const int tid = threadIdx.x;           // 256 threads
    const int tx  = tid & 15, ty = tid >> 4;
    const int m0  = blockIdx.x * 64, n0 = blockIdx.y * 64;
    const int am  = tid & 63;              // element index for loads
    const int ak0 = (tid >> 6) << 2;       // k sub-offset (0,4,8,12)

    float acc[4][4] = {};

    const int  gm   = m0 + am;
    const bool mval = (gm < M);
    int r = 0;
    if (MODE == 0) r = mval ? erow[gm] : 0;   // hoist gather index

    for (int k0 = 0; k0 < K; k0 += 16) {
        // ---- load A tile (gathered / fused) ----
        #pragma unroll
        for (int i = 0; i < 4; i++) {
            int gk = k0 + ak0 + i;
            float v = 0.f;
            if (mval && gk < K) {
                if (MODE == 0) {
                    if (gk < NFD)       v = x[(size_t)r * NFD + gk];
                    else if (gk == NFD) v = (float)batch[r];
                    else                v = eattr[(size_t)gm * EFD + (gk - NFD - 1)];
                } else if (MODE == 1) {
                    if (gk < NFD)       v = x[(size_t)gm * NFD + gk];
                    else if (gk == NFD) v = (float)batch[gm];
                    else                v = agg[(size_t)gm * LL + (gk - NFD - 1)];
                } else {
                    float y = Y2[(size_t)gm * DD2 + gk];
                    v = fmaxf(fmaf(y, scale[gk], shift[gk]), 0.f);
                }
            }
            As[ak0 + i][am] = v;
        }
        // ---- load B tile ----
        #pragma unroll
        for (int i = 0; i < 4; i++) {
            int gk = k0 + ak0 + i;
            int gn = n0 + am;
            Bs[ak0 + i][am] = (gk < K && gn < Nc) ? B[(size_t)gk * Nc + gn] : 0.f;
        }
        __syncthreads();
        // ---- 4x4 micro-tile FFMA ----
        #pragma unroll
        for (int kk = 0; kk < 16; kk++) {
            float4 av = *reinterpret_cast<const float4*>(&As[kk][ty << 2]);
            float4 bv = *reinterpret_cast<const float4*>(&Bs[kk][tx << 2]);
            float a[4] = {av.x, av.y, av.z, av.w};
            float b[4] = {bv.x, bv.y, bv.z, bv.w};
            #pragma unroll
            for (int i = 0; i < 4; i++)
                #pragma unroll
                for (int j = 0; j < 4; j++)
                    acc[i][j] = fmaf(a[i], b[j], acc[i][j]);
        }
        __syncthreads();
    }
    // ---- epilogue: bias (+ optional relu) ----
    #pragma unroll
    for (int i = 0; i < 4; i++) {
        int gmi = m0 + (ty << 2) + i;
        if (gmi >= M) continue;
        #pragma unroll
        for (int j = 0; j < 4; j++) {
            int gn = n0 + (tx << 2) + j;
            if (gn >= Nc) continue;
            float v = acc[i][j] + bias[gn];
            if (relu_out) v = fmaxf(v, 0.f);
            C[(size_t)gmi * Nc + gn] = v;
        }
    }
}

// ---------------- per-column sum / sumsq over rows (for BatchNorm) ----------
__global__ void colstats_kernel(const float* __restrict__ Y, int M, int C, int rpb,
                                float* __restrict__ sum, float* __restrict__ sumsq)
{
    int r0 = blockIdx.x * rpb;
    int r1 = min(M, r0 + rpb);
    int c0 = threadIdx.x, c1 = threadIdx.x + 256;   // C <= 512
    float s0 = 0, q0 = 0, s1 = 0, q1 = 0;
    for (int rr = r0; rr < r1; rr++) {
        const float* p = Y + (size_t)rr * C;
        if (c0 < C) { float v = p[c0]; s0 += v; q0 += v * v; }
        if (c1 < C) { float v = p[c1]; s1 += v; q1 += v * v; }
    }
    if (c0 < C) { atomicAdd(&sum[c0], s0); atomicAdd(&sumsq[c0], q0); }
    if (c1 < C) { atomicAdd(&sum[c1], s1); atomicAdd(&sumsq[c1], q1); }
}

// fold BN affine into scale/shift:  bn(y) = y*scale + shift
__global__ void finalize_kernel(const float* __restrict__ sum, const float* __restrict__ sumsq,
                                int M, int C,
                                const float* __restrict__ gamma, const float* __restrict__ beta,
                                float* __restrict__ scale, float* __restrict__ shift)
{
    int c = blockIdx.x * blockDim.x + threadIdx.x;
    if (c < C) {
        float mu  = sum[c] / (float)M;
        float var = sumsq[c] / (float)M - mu * mu;
        float sc  = rsqrtf(var + BNEPS) * gamma[c];
        scale[c] = sc;
        shift[c] = beta[c] - mu * sc;
    }
}

__global__ void cnt_kernel(const int* __restrict__ col, int* __restrict__ cnt)
{
    int e = blockIdx.x * blockDim.x + threadIdx.x;
    if (e < NE) atomicAdd(&cnt[col[e]], 1);
}

// apply BN+relu to Y1 rows and scatter-add onto destination nodes
__global__ void scatter_kernel(const float* __restrict__ Y1, const int* __restrict__ col,
                               const float* __restrict__ scale, const float* __restrict__ shift,
                               float* __restrict__ ssum)
{
    int t = threadIdx.x;               // column 0..255
    float sc = scale[t], sh = shift[t];
    int e0 = blockIdx.x * 16;          // 16 edges per block
    #pragma unroll 4
    for (int i = 0; i < 16; i++) {
        int e = e0 + i;
        float v = fmaxf(fmaf(Y1[(size_t)e * LL + t], sc, sh), 0.f);
        int c = col[e];
        atomicAdd(&ssum[(size_t)c * LL + t], v);
    }
}

// ssum -> mean (divide by count)
__global__ void aggdiv_kernel(float* __restrict__ ssum, const int* __restrict__ cnt)
{
    size_t idx = (size_t)blockIdx.x * blockDim.x + threadIdx.x;
    if (idx < (size_t)NN * LL) {
        int rr = (int)(idx >> 8);      // LL == 256
        ssum[idx] *= (1.0f / (float)max(cnt[rr], 1));
    }
}

extern "C" void kernel_launch(void* const* d_in, const int* in_sizes, int n_in,
                              void* d_out, int out_size)
{
    const float* x     = (const float*)d_in[0];
    const int*   eidx  = (const int*)  d_in[1];
    const float* eattr = (const float*)d_in[2];
    // d_in[3] = u (unused by the model)
    const int*   batch = (const int*)  d_in[4];
    const float* W1  = (const float*)d_in[5];
    const float* b1  = (const float*)d_in[6];
    const float* g1  = (const float*)d_in[7];
    const float* be1 = (const float*)d_in[8];
    const float* W2  = (const float*)d_in[9];
    const float* b2  = (const float*)d_in[10];
    const float* g2  = (const float*)d_in[11];
    const float* be2 = (const float*)d_in[12];
    const float* W3  = (const float*)d_in[13];
    const float* b3  = (const float*)d_in[14];
    float* out = (float*)d_out;

    const int* erow = eidx;        // edge_index[0]
    const int* ecol = eidx + NE;   // edge_index[1]

    void *pY1, *pY2, *pss, *pcnt;
    void *ps1, *pq1, *psc1, *psh1, *ps2, *pq2, *psc2, *psh2;
    cudaGetSymbolAddress(&pY1,  g_Y1);
    cudaGetSymbolAddress(&pY2,  g_Y2);
    cudaGetSymbolAddress(&pss,  g_ssum);
    cudaGetSymbolAddress(&pcnt, g_cnt);
    cudaGetSymbolAddress(&ps1,  g_sum1);  cudaGetSymbolAddress(&pq1,  g_sumsq1);
    cudaGetSymbolAddress(&psc1, g_scale1); cudaGetSymbolAddress(&psh1, g_shift1);
    cudaGetSymbolAddress(&ps2,  g_sum2);  cudaGetSymbolAddress(&pq2,  g_sumsq2);
    cudaGetSymbolAddress(&psc2, g_scale2); cudaGetSymbolAddress(&psh2, g_shift2);

    cudaMemsetAsync(ps1,  0, LL  * sizeof(float), 0);
    cudaMemsetAsync(pq1,  0, LL  * sizeof(float), 0);
    cudaMemsetAsync(ps2,  0, DD2 * sizeof(float), 0);
    cudaMemsetAsync(pq2,  0, DD2 * sizeof(float), 0);
    cudaMemsetAsync(pcnt, 0, NN  * sizeof(int),   0);
    cudaMemsetAsync(pss,  0, (size_t)NN * LL * sizeof(float), 0);

    dim3 blk(256);

    // 1) edge GEMM: Y1[E,256] = concat(x[row],batch[row],eattr) @ W1 + b1
    gemm_kernel<0><<<dim3(NE / 64, LL / 64), blk>>>(
        NE, LL, DD1, W1, b1, (float*)pY1,
        x, erow, eattr, batch, nullptr, nullptr, nullptr, nullptr, 0);

    // 2) BN stats over E rows
    colstats_kernel<<<(NE + 1023) / 1024, 256>>>((float*)pY1, NE, LL, 1024,
                                                 (float*)ps1, (float*)pq1);
    finalize_kernel<<<2, 256>>>((float*)ps1, (float*)pq1, NE, LL, g1, be1,
                                (float*)psc1, (float*)psh1);

    // 3) scatter-mean (BN+relu applied on the fly)
    cnt_kernel<<<NE / 256, 256>>>(ecol, (int*)pcnt);
    scatter_kernel<<<NE / 16, 256>>>((float*)pY1, ecol,
                                     (float*)psc1, (float*)psh1, (float*)pss);
    aggdiv_kernel<<<(NN * LL) / 256, 256>>>((float*)pss, (int*)pcnt);

    // 4) node GEMM: Y2[N,385] = concat(x,batch,agg) @ W2 + b2
    gemm_kernel<1><<<dim3((NN + 63) / 64, (DD2 + 63) / 64), blk>>>(
        NN, DD2, DD2, W2, b2, (float*)pY2,
        x, nullptr, nullptr, batch, (float*)pss, nullptr, nullptr, nullptr, 0);

    // 5) BN stats over N rows
    colstats_kernel<<<(NN + 255) / 256, 256>>>((float*)pY2, NN, DD2, 256,
                                               (float*)ps2, (float*)pq2);
    finalize_kernel<<<2, 256>>>((float*)ps2, (float*)pq2, NN, DD2, g2, be2,
                                (float*)psc2, (float*)psh2);

    // 6) output GEMM: out = relu(relu(bn(Y2)) @ W3 + b3)
    gemm_kernel<2><<<dim3((NN + 63) / 64, NFD / 64), blk>>>(
        NN, NFD, DD2, W3, b3, out,
        nullptr, nullptr, nullptr, nullptr, nullptr,
        (float*)pY2, (float*)psc2, (float*)psh2, 1);
}

// round 2
// speedup vs baseline: 1.8562x; 1.8562x over previous
#include <cuda_runtime.h>
#include <math.h>

#define NN   50000      // nodes
#define NE   800000     // edges
#define NFD  128        // node feature size
#define EFD  64         // edge feature size
#define LL   256        // layer size (mlp1 out)
#define DD1  193        // mlp1 input dim
#define DD2  385        // mlp2 dim
#define BNEPS 1e-5f

// ---------------- scratch (static device globals) ---------------------------
__device__ float g_Y1[(size_t)NE * LL];     // edge MLP pre-BN output
__device__ float g_Y2[(size_t)NN * DD2];    // node MLP pre-BN output
__device__ float g_ssum[(size_t)NN * LL];   // aggregated means
__device__ int   g_cnt[NN];
__device__ int   g_off[NN + 1];             // CSR offsets
__device__ int   g_cur[NN];                 // bucket cursors
__device__ int   g_eid[NE];                 // edge ids sorted by dst
__device__ float g_sum1[LL],  g_sumsq1[LL],  g_scale1[LL],  g_shift1[LL];
__device__ float g_sum2[DD2], g_sumsq2[DD2], g_scale2[DD2], g_shift2[DD2];

// ---------------- tf32 helpers ----------------------------------------------
__device__ __forceinline__ unsigned f2tf(float f) {
    unsigned r;
    asm("cvt.rna.tf32.f32 %0, %1;" : "=r"(r) : "f"(f));
    return r;
}
__device__ __forceinline__ void mma_tf32(float* c, unsigned a0, unsigned a1,
                                         unsigned a2, unsigned a3,
                                         unsigned b0, unsigned b1) {
    asm volatile(
        "mma.sync.aligned.m16n8k8.row.col.f32.tf32.tf32.f32 "
        "{%0,%1,%2,%3},{%4,%5,%6,%7},{%8,%9},{%0,%1,%2,%3};"
        : "+f"(c[0]), "+f"(c[1]), "+f"(c[2]), "+f"(c[3])
        : "r"(a0), "r"(a1), "r"(a2), "r"(a3), "r"(b0), "r"(b1));
}

// ---------------- TF32 tensor-core GEMM: C[M,Nc] = A[M,K] @ B[K,Nc] + bias --
// Block tile 128(M) x 64(N), 8 warps (4 along M x 2 along N), k-tile 16.
// A rows are generated on the fly per MODE:
//   MODE 0: edge rows  = [x[erow[m]], batch[erow[m]], eattr[m]]
//   MODE 1: node rows  = [x[m], batch[m], agg[m]]
//   MODE 2: relu(bn(Y2[m]))  (scale/shift precomputed)
template<int MODE>
__global__ void __launch_bounds__(256) gemm_tf32(int M, int Nc, int K,
    const float* __restrict__ B, const float* __restrict__ bias,
    float* __restrict__ C,
    const float* __restrict__ x, const int* __restrict__ erow,
    const float* __restrict__ eattr, const int* __restrict__ batch,
    const float* __restrict__ agg,
    const float* __restrict__ Y2,
    const float* __restrict__ scale, const float* __restrict__ shift,
    int relu_out)
{
    __shared__ unsigned As[128][17];   // [m][k], pad 17 -> conflict-free
    __shared__ unsigned Bs[64][17];    // [n][k]
    __shared__ int rIdx[128];

    const int tid  = threadIdx.x;
    const int wid  = tid >> 5, lane = tid & 31;
    const int gid  = lane >> 2, tg = lane & 3;
    const int m0   = blockIdx.x * 128, n0 = blockIdx.y * 64;
    const int wm   = (wid & 3) * 32;   // warp offset in M
    const int wn   = (wid >> 2) * 32;  // warp offset in N

    float c[2][4][4];
    #pragma unroll
    for (int i = 0; i < 2; i++)
        #pragma unroll
        for (int j = 0; j < 4; j++)
            #pragma unroll
            for (int k = 0; k < 4; k++) c[i][j][k] = 0.f;

    if (MODE == 0) {
        if (tid < 128) {
            int gm = m0 + tid;
            rIdx[tid] = (gm < M) ? erow[gm] : 0;
        }
        __syncthreads();
    }

    const int kk = tid & 15;        // A-gen k lane
    const int mb = tid >> 4;        // A-gen m base (0..15)
    const int bn = tid & 63;        // B-load n lane
    const int bk = tid >> 6;        // B-load k base (0..3)

    for (int k0 = 0; k0 < K; k0 += 16) {
        // ---- generate A tile [128 x 16] ----
        int gk = k0 + kk;
        #pragma unroll
        for (int i = 0; i < 8; i++) {
            int mm = mb + i * 16;
            int gm = m0 + mm;
            float v = 0.f;
            if (gm < M && gk < K) {
                if (MODE == 0) {
                    int r = rIdx[mm];
                    if (gk < NFD)       v = x[(size_t)r * NFD + gk];
                    else if (gk == NFD) v = (float)batch[r];
                    else                v = eattr[(size_t)gm * EFD + (gk - NFD - 1)];
                } else if (MODE == 1) {
                    if (gk < NFD)       v = x[(size_t)gm * NFD + gk];
                    else if (gk == NFD) v = (float)batch[gm];
                    else                v = agg[(size_t)gm * LL + (gk - NFD - 1)];
                } else {
                    float y = Y2[(size_t)gm * DD2 + gk];
                    v = fmaxf(fmaf(y, scale[gk], shift[gk]), 0.f);
                }
            }
            As[mm][kk] = f2tf(v);
        }
        // ---- load B tile [16 x 64] ----
        #pragma unroll
        for (int i = 0; i < 4; i++) {
            int k = bk + i * 4;
            int gkb = k0 + k;
            int gn = n0 + bn;
            float v = (gkb < K && gn < Nc) ? B[(size_t)gkb * Nc + gn] : 0.f;
            Bs[bn][k] = f2tf(v);
        }
        __syncthreads();

        // ---- two k8 steps ----
        #pragma unroll
        for (int ks = 0; ks < 16; ks += 8) {
            unsigned a[2][4], b[4][2];
            #pragma unroll
            for (int mt = 0; mt < 2; mt++) {
                int r = wm + mt * 16;
                a[mt][0] = As[r + gid][ks + tg];
                a[mt][1] = As[r + gid + 8][ks + tg];
                a[mt][2] = As[r + gid][ks + tg + 4];
                a[mt][3] = As[r + gid + 8][ks + tg + 4];
            }
            #pragma unroll
            for (int nt = 0; nt < 4; nt++) {
                int cc = wn + nt * 8;
                b[nt][0] = Bs[cc + gid][ks + tg];
                b[nt][1] = Bs[cc + gid][ks + tg + 4];
            }
            #pragma unroll
            for (int mt = 0; mt < 2; mt++)
                #pragma unroll
                for (int nt = 0; nt < 4; nt++)
                    mma_tf32(c[mt][nt], a[mt][0], a[mt][1], a[mt][2], a[mt][3],
                             b[nt][0], b[nt][1]);
        }
        __syncthreads();
    }

    // ---- epilogue: bias (+relu) ----
    #pragma unroll
    for (int mt = 0; mt < 2; mt++) {
        int r0 = m0 + wm + mt * 16 + gid;
        int r1 = r0 + 8;
        #pragma unroll
        for (int nt = 0; nt < 4; nt++) {
            int cb = n0 + wn + nt * 8 + 2 * tg;
            #pragma unroll
            for (int h = 0; h < 2; h++) {
                int col = cb + h;
                if (col >= Nc) continue;
                float bb = bias[col];
                if (r0 < M) {
                    float v = c[mt][nt][h] + bb;
                    if (relu_out) v = fmaxf(v, 0.f);
                    C[(size_t)r0 * Nc + col] = v;
                }
                if (r1 < M) {
                    float v = c[mt][nt][2 + h] + bb;
                    if (relu_out) v = fmaxf(v, 0.f);
                    C[(size_t)r1 * Nc + col] = v;
                }
            }
        }
    }
}

// ---------------- per-column sum / sumsq over rows (for BatchNorm) ----------
__global__ void colstats_kernel(const float* __restrict__ Y, int M, int C, int rpb,
                                float* __restrict__ sum, float* __restrict__ sumsq)
{
    int r0 = blockIdx.x * rpb;
    int r1 = min(M, r0 + rpb);
    int c0 = threadIdx.x, c1 = threadIdx.x + 256;
    float s0 = 0, q0 = 0, s1 = 0, q1 = 0;
    for (int rr = r0; rr < r1; rr++) {
        const float* p = Y + (size_t)rr * C;
        if (c0 < C) { float v = p[c0]; s0 += v; q0 += v * v; }
        if (c1 < C) { float v = p[c1]; s1 += v; q1 += v * v; }
    }
    if (c0 < C) { atomicAdd(&sum[c0], s0); atomicAdd(&sumsq[c0], q0); }
    if (c1 < C) { atomicAdd(&sum[c1], s1); atomicAdd(&sumsq[c1], q1); }
}

__global__ void finalize_kernel(const float* __restrict__ sum, const float* __restrict__ sumsq,
                                int M, int C,
                                const float* __restrict__ gamma, const float* __restrict__ beta,
                                float* __restrict__ scale, float* __restrict__ shift)
{
    int c = blockIdx.x * blockDim.x + threadIdx.x;
    if (c < C) {
        float mu  = sum[c] / (float)M;
        float var = sumsq[c] / (float)M - mu * mu;
        float sc  = rsqrtf(var + BNEPS) * gamma[c];
        scale[c] = sc;
        shift[c] = beta[c] - mu * sc;
    }
}

__global__ void cnt_kernel(const int* __restrict__ col, int* __restrict__ cnt)
{
    int e = blockIdx.x * blockDim.x + threadIdx.x;
    if (e < NE) atomicAdd(&cnt[col[e]], 1);
}

// single-block exclusive scan of counts -> CSR offsets (+cursor copy)
__global__ void scan_kernel(const int* __restrict__ cnt,
                            int* __restrict__ off, int* __restrict__ cur)
{
    __shared__ int warpsum[32];
    __shared__ int base_s;
    int tid = threadIdx.x, lane = tid & 31, w = tid >> 5;
    if (tid == 0) base_s = 0;
    __syncthreads();
    for (int c0 = 0; c0 < NN; c0 += 1024) {
        int i = c0 + tid;
        int v = (i < NN) ? cnt[i] : 0;
        int inc = v;
        #pragma unroll
        for (int s = 1; s < 32; s <<= 1) {
            int t = __shfl_up_sync(0xffffffffu, inc, s);
            if (lane >= s) inc += t;
        }
        if (lane == 31) warpsum[w] = inc;
        __syncthreads();
        if (w == 0) {
            int ws = warpsum[lane];
            #pragma unroll
            for (int s = 1; s < 32; s <<= 1) {
                int t = __shfl_up_sync(0xffffffffu, ws, s);
                if (lane >= s) ws += t;
            }
            warpsum[lane] = ws;
        }
        __syncthreads();
        int base = base_s;
        int wexc = (w > 0) ? warpsum[w - 1] : 0;
        int excl = base + wexc + inc - v;
        if (i < NN) { off[i] = excl; cur[i] = excl; }
        int total = warpsum[31];
        __syncthreads();
        if (tid == 0) base_s = base + total;
        __syncthreads();
    }
    if (threadIdx.x == 0) off[NN] = base_s;
}

// bucket edge ids by destination node
__global__ void bucket_kernel(const int* __restrict__ col,
                              int* __restrict__ cur, int* __restrict__ eid)
{
    int e = blockIdx.x * blockDim.x + threadIdx.x;
    if (e < NE) {
        int pos = atomicAdd(&cur[col[e]], 1);
        eid[pos] = e;
    }
}

// per-node gather-sum of relu(bn(Y1)) rows, then mean
__global__ void gather_kernel(const float* __restrict__ Y1,
                              const int* __restrict__ eid, const int* __restrict__ off,
                              const float* __restrict__ scale, const float* __restrict__ shift,
                              float* __restrict__ ssum)
{
    int n = blockIdx.x;
    int t = threadIdx.x;          // column 0..255
    int s = off[n], e = off[n + 1];
    float sc = scale[t], sh = shift[t];
    float a0 = 0, a1 = 0, a2 = 0, a3 = 0;
    int j = s;
    for (; j + 4 <= e; j += 4) {
        int e0 = eid[j], e1 = eid[j + 1], e2 = eid[j + 2], e3 = eid[j + 3];
        float y0 = Y1[(size_t)e0 * LL + t];
        float y1 = Y1[(size_t)e1 * LL + t];
        float y2 = Y1[(size_t)e2 * LL + t];
        float y3 = Y1[(size_t)e3 * LL + t];
        a0 += fmaxf(fmaf(y0, sc, sh), 0.f);
        a1 += fmaxf(fmaf(y1, sc, sh), 0.f);
        a2 += fmaxf(fmaf(y2, sc, sh), 0.f);
        a3 += fmaxf(fmaf(y3, sc, sh), 0.f);
    }
    for (; j < e; j++) {
        float y = Y1[(size_t)eid[j] * LL + t];
        a0 += fmaxf(fmaf(y, sc, sh), 0.f);
    }
    float acc = (a0 + a1) + (a2 + a3);
    float inv = 1.f / (float)max(e - s, 1);
    ssum[(size_t)n * LL + t] = acc * inv;
}

extern "C" void kernel_launch(void* const* d_in, const int* in_sizes, int n_in,
                              void* d_out, int out_size)
{
    const float* x     = (const float*)d_in[0];
    const int*   eidx  = (const int*)  d_in[1];
    const float* eattr = (const float*)d_in[2];
    const int*   batch = (const int*)  d_in[4];
    const float* W1  = (const float*)d_in[5];
    const float* b1  = (const float*)d_in[6];
    const float* g1  = (const float*)d_in[7];
    const float* be1 = (const float*)d_in[8];
    const float* W2  = (const float*)d_in[9];
    const float* b2  = (const float*)d_in[10];
    const float* g2  = (const float*)d_in[11];
    const float* be2 = (const float*)d_in[12];
    const float* W3  = (const float*)d_in[13];
    const float* b3  = (const float*)d_in[14];
    float* out = (float*)d_out;

    const int* erow = eidx;
    const int* ecol = eidx + NE;

    void *pY1, *pY2, *pss, *pcnt, *poff, *pcur, *peid;
    void *ps1, *pq1, *psc1, *psh1, *ps2, *pq2, *psc2, *psh2;
    cudaGetSymbolAddress(&pY1,  g_Y1);
    cudaGetSymbolAddress(&pY2,  g_Y2);
    cudaGetSymbolAddress(&pss,  g_ssum);
    cudaGetSymbolAddress(&pcnt, g_cnt);
    cudaGetSymbolAddress(&poff, g_off);
    cudaGetSymbolAddress(&pcur, g_cur);
    cudaGetSymbolAddress(&peid, g_eid);
    cudaGetSymbolAddress(&ps1,  g_sum1);   cudaGetSymbolAddress(&pq1,  g_sumsq1);
    cudaGetSymbolAddress(&psc1, g_scale1); cudaGetSymbolAddress(&psh1, g_shift1);
    cudaGetSymbolAddress(&ps2,  g_sum2);   cudaGetSymbolAddress(&pq2,  g_sumsq2);
    cudaGetSymbolAddress(&psc2, g_scale2); cudaGetSymbolAddress(&psh2, g_shift2);

    cudaMemsetAsync(ps1,  0, LL  * sizeof(float), 0);
    cudaMemsetAsync(pq1,  0, LL  * sizeof(float), 0);
    cudaMemsetAsync(ps2,  0, DD2 * sizeof(float), 0);
    cudaMemsetAsync(pq2,  0, DD2 * sizeof(float), 0);
    cudaMemsetAsync(pcnt, 0, NN  * sizeof(int),   0);

    dim3 blk(256);

    // 1) edge GEMM: Y1[E,256] = concat(x[row],batch[row],eattr) @ W1 + b1
    gemm_tf32<0><<<dim3(NE / 128, LL / 64), blk>>>(
        NE, LL, DD1, W1, b1, (float*)pY1,
        x, erow, eattr, batch, nullptr, nullptr, nullptr, nullptr, 0);

    // 2) BN1 stats
    colstats_kernel<<<(NE + 1023) / 1024, 256>>>((float*)pY1, NE, LL, 1024,
                                                 (float*)ps1, (float*)pq1);
    finalize_kernel<<<2, 256>>>((float*)ps1, (float*)pq1, NE, LL, g1, be1,
                                (float*)psc1, (float*)psh1);

    // 3) CSR build + gather-mean (BN+relu applied on the fly)
    cnt_kernel<<<NE / 256, 256>>>(ecol, (int*)pcnt);
    scan_kernel<<<1, 1024>>>((int*)pcnt, (int*)poff, (int*)pcur);
    bucket_kernel<<<NE / 256, 256>>>(ecol, (int*)pcur, (int*)peid);
    gather_kernel<<<NN, 256>>>((float*)pY1, (int*)peid, (int*)poff,
                               (float*)psc1, (float*)psh1, (float*)pss);

    // 4) node GEMM: Y2[N,385] = concat(x,batch,agg) @ W2 + b2
    gemm_tf32<1><<<dim3((NN + 127) / 128, (DD2 + 63) / 64), blk>>>(
        NN, DD2, DD2, W2, b2, (float*)pY2,
        x, nullptr, nullptr, batch, (float*)pss, nullptr, nullptr, nullptr, 0);

    // 5) BN2 stats
    colstats_kernel<<<(NN + 255) / 256, 256>>>((float*)pY2, NN, DD2, 256,
                                               (float*)ps2, (float*)pq2);
    finalize_kernel<<<2, 256>>>((float*)ps2, (float*)pq2, NN, DD2, g2, be2,
                                (float*)psc2, (float*)psh2);

    // 6) output GEMM: out = relu(relu(bn(Y2)) @ W3 + b3)
    gemm_tf32<2><<<dim3((NN + 127) / 128, NFD / 64), blk>>>(
        NN, NFD, DD2, W3, b3, out,
        nullptr, nullptr, nullptr, nullptr, nullptr,
        (float*)pY2, (float*)psc2, (float*)psh2, 1);
}

// round 6
// speedup vs baseline: 3.2402x; 1.7457x over previous
#include <cuda_runtime.h>
#include <cstdint>
#include <math.h>

#define NN   50000      // nodes
#define NE   800000     // edges
#define NFD  128        // node feature size
#define EFD  64         // edge feature size
#define LL   256        // layer size (mlp1 out)
#define DD1  193        // mlp1 input dim
#define DD2  385        // mlp2 dim
#define KXW  129        // x + batch part of mlp1 K
#define BNEPS 1e-5f

// ---------------- scratch (static device globals) ---------------------------
__device__ float    g_Y1[(size_t)NE * LL];     // edge MLP pre-BN output
__device__ float    g_Y2[(size_t)NN * DD2];    // node MLP pre-BN output
__device__ float    g_XW[(size_t)NN * LL];     // node part of edge MLP
__device__ float    g_ssum[(size_t)NN * LL];   // aggregated means
__device__ uint32_t g_W1e[LL * EFD];           // W1[129:193]^T as tf32, [n][k]
__device__ int      g_cnt[NN];
__device__ int      g_off[NN + 1];
__device__ int      g_cur[NN];
__device__ int      g_eid[NE];
__device__ float    g_sum1[LL],  g_sumsq1[LL],  g_scale1[LL],  g_shift1[LL];
__device__ float    g_sum2[DD2], g_sumsq2[DD2], g_scale2[DD2], g_shift2[DD2];

// ---------------- tf32 helpers ----------------------------------------------
__device__ __forceinline__ unsigned f2tf(float f) {
    unsigned r;
    asm("cvt.rna.tf32.f32 %0, %1;" : "=r"(r) : "f"(f));
    return r;
}
__device__ __forceinline__ void mma_w(float* c, unsigned a0, unsigned a1,
                                      unsigned a2, unsigned a3, unsigned b0, unsigned b1) {
    asm volatile(
        "mma.sync.aligned.m16n8k8.row.col.f32.tf32.tf32.f32 "
        "{%0,%1,%2,%3},{%4,%5,%6,%7},{%8,%9},{%0,%1,%2,%3};"
        : "+f"(c[0]), "+f"(c[1]), "+f"(c[2]), "+f"(c[3])
        : "r"(a0), "r"(a1), "r"(a2), "r"(a3), "r"(b0), "r"(b1));
}

// ---------------- prep: W1[129:193]^T -> tf32 [n][k] ------------------------
__global__ void prep_W1e(const float* __restrict__ W1, uint32_t* __restrict__ W1e)
{
    int idx = blockIdx.x * 256 + threadIdx.x;    // LL*EFD = 16384
    if (idx >= LL * EFD) return;
    int n = idx >> 6, k = idx & 63;
    W1e[idx] = f2tf(W1[(size_t)(KXW + k) * LL + n]);
}

// ---------------- edge GEMM (K=64) + XW gather-add + fused BN1 stats --------
// grid = NE/128 blocks, 256 threads. Loops over the 4 column tiles of LL=256.
// smem offsets (bytes); all row strides 68 floats = 272B (16-byte aligned).
#define ESA    0                         // As: eattr tf32 [128][68] = 34816
#define ESB    34816                     // Bs: W1e tile   [64][68]  = 17408
#define ESXW   52224                     // XWs: gathered  [128][68] = 34816
#define ESRIDX 87040                     // rIdx[128] = 512
#define ESSTAT 87552                     // sum[256], sq[256] = 2048
#define E_SMEM 89600

__global__ void __launch_bounds__(256) edge_gemm(
    const float* __restrict__ eattr, const int* __restrict__ erow,
    const uint32_t* __restrict__ W1e, const float* __restrict__ XW,
    float* __restrict__ Y1,
    float* __restrict__ gsum, float* __restrict__ gsq)
{
    extern __shared__ char smem[];
    uint32_t (*As)[68]  = (uint32_t(*)[68])(smem + ESA);
    uint32_t (*Bs)[68]  = (uint32_t(*)[68])(smem + ESB);
    float    (*XWs)[68] = (float(*)[68])   (smem + ESXW);
    int*   rIdx = (int*)  (smem + ESRIDX);
    float* sSum = (float*)(smem + ESSTAT);
    float* sSq  = (float*)(smem + ESSTAT + 1024);

    const int tid  = threadIdx.x;
    const int wid  = tid >> 5, lane = tid & 31;
    const int gid  = lane >> 2, tg = lane & 3;
    const int m0   = blockIdx.x * 128;
    const int wm   = (wid & 3) * 32;     // warp row offset
    const int wn   = (wid >> 2) * 32;    // warp col offset within 64-tile

    // stage eattr tile [128 x 64] as tf32 (coalesced float4)
    #pragma unroll
    for (int it = 0; it < 8; it++) {
        int idx = tid + it * 256;        // 0..2047
        int row = idx >> 4, q = idx & 15;
        float4 v = *(const float4*)(eattr + (size_t)(m0 + row) * EFD + 4 * q);
        uint4 t; t.x = f2tf(v.x); t.y = f2tf(v.y); t.z = f2tf(v.z); t.w = f2tf(v.w);
        *(uint4*)&As[row][4 * q] = t;
    }
    if (tid < 128) rIdx[tid] = erow[m0 + tid];
    sSum[tid] = 0.f; sSq[tid] = 0.f;
    __syncthreads();

    for (int ct = 0; ct < 4; ct++) {
        const int n0 = ct * 64;
        // load B tile [64 x 64] (pre-converted tf32, [n][k])
        #pragma unroll
        for (int it = 0; it < 4; it++) {
            int idx = tid + it * 256;    // 0..1023
            int n = idx >> 4, q = idx & 15;
            uint4 t = *(const uint4*)(W1e + (size_t)(n0 + n) * EFD + 4 * q);
            *(uint4*)&Bs[n][4 * q] = t;
        }
        // stage XW tile [128 x 64] (coalesced rows)
        #pragma unroll
        for (int it = 0; it < 8; it++) {
            int idx = tid + it * 256;
            int row = idx >> 4, q = idx & 15;
            float4 v = *(const float4*)(XW + (size_t)rIdx[row] * LL + n0 + 4 * q);
            *(float4*)&XWs[row][4 * q] = v;
        }
        __syncthreads();

        // compute 128x64, K=64
        float c[2][4][4];
        #pragma unroll
        for (int i = 0; i < 2; i++)
            #pragma unroll
            for (int j = 0; j < 4; j++)
                #pragma unroll
                for (int k = 0; k < 4; k++) c[i][j][k] = 0.f;

        #pragma unroll
        for (int ks = 0; ks < 64; ks += 8) {
            unsigned a[2][4], b[4][2];
            #pragma unroll
            for (int mt = 0; mt < 2; mt++) {
                int r = wm + mt * 16;
                a[mt][0] = As[r + gid][ks + tg];
                a[mt][1] = As[r + gid + 8][ks + tg];
                a[mt][2] = As[r + gid][ks + tg + 4];
                a[mt][3] = As[r + gid + 8][ks + tg + 4];
            }
            #pragma unroll
            for (int nt = 0; nt < 4; nt++) {
                int cc = wn + nt * 8;
                b[nt][0] = Bs[cc + gid][ks + tg];
                b[nt][1] = Bs[cc + gid][ks + tg + 4];
            }
            #pragma unroll
            for (int mt = 0; mt < 2; mt++)
                #pragma unroll
                for (int nt = 0; nt < 4; nt++)
                    mma_w(c[mt][nt], a[mt][0], a[mt][1], a[mt][2], a[mt][3],
                          b[nt][0], b[nt][1]);
        }

        // epilogue: add gathered XW rows, write Y1, accumulate BN stats
        float ls[8], lq[8];
        #pragma unroll
        for (int s = 0; s < 8; s++) { ls[s] = 0.f; lq[s] = 0.f; }
        #pragma unroll
        for (int mt = 0; mt < 2; mt++) {
            int r0 = wm + mt * 16 + gid;
            int r1 = r0 + 8;
            #pragma unroll
            for (int nt = 0; nt < 4; nt++) {
                int cb = wn + nt * 8 + 2 * tg;
                float v00 = c[mt][nt][0] + XWs[r0][cb];
                float v01 = c[mt][nt][1] + XWs[r0][cb + 1];
                float v10 = c[mt][nt][2] + XWs[r1][cb];
                float v11 = c[mt][nt][3] + XWs[r1][cb + 1];
                float2 o0 = make_float2(v00, v01);
                float2 o1 = make_float2(v10, v11);
                *(float2*)(Y1 + (size_t)(m0 + r0) * LL + n0 + cb) = o0;
                *(float2*)(Y1 + (size_t)(m0 + r1) * LL + n0 + cb) = o1;
                ls[nt * 2 + 0] += v00 + v10;  lq[nt * 2 + 0] += v00 * v00 + v10 * v10;
                ls[nt * 2 + 1] += v01 + v11;  lq[nt * 2 + 1] += v01 * v01 + v11 * v11;
            }
        }
        // shuffle-reduce over gid (lane bits 2..4), then lanes gid==0 commit
        #pragma unroll
        for (int mask = 4; mask <= 16; mask <<= 1)
            #pragma unroll
            for (int s = 0; s < 8; s++) {
                ls[s] += __shfl_xor_sync(0xffffffffu, ls[s], mask);
                lq[s] += __shfl_xor_sync(0xffffffffu, lq[s], mask);
            }
        if (gid == 0) {
            #pragma unroll
            for (int nt = 0; nt < 4; nt++)
                #pragma unroll
                for (int h = 0; h < 2; h++) {
                    int col = n0 + wn + nt * 8 + 2 * tg + h;
                    atomicAdd(&sSum[col], ls[nt * 2 + h]);
                    atomicAdd(&sSq[col],  lq[nt * 2 + h]);
                }
        }
        __syncthreads();
    }
    atomicAdd(&gsum[tid], sSum[tid]);
    atomicAdd(&gsq[tid],  sSq[tid]);
}

// ---------------- generic warp-mma TF32 GEMM (modes 1,2,3) ------------------
//   MODE 1: node rows  = [x[m], batch[m], agg[m]]            (Y2 pre-BN)
//   MODE 2: relu(bn(Y2[m])) (scale/shift precomputed)        (output)
//   MODE 3: xw rows    = [x[m], batch[m]]                    (XW)
template<int MODE>
__global__ void __launch_bounds__(256) gemm_tf32(int M, int Nc, int K,
    const float* __restrict__ B, const float* __restrict__ bias,
    float* __restrict__ C,
    const float* __restrict__ x, const int* __restrict__ batch,
    const float* __restrict__ agg,
    const float* __restrict__ Y2,
    const float* __restrict__ scale, const float* __restrict__ shift,
    int relu_out)
{
    __shared__ unsigned As[128][17];
    __shared__ unsigned Bs[64][17];

    const int tid = threadIdx.x;
    const int wid = tid >> 5, lane = tid & 31;
    const int gid = lane >> 2, tg = lane & 3;
    const int m0  = blockIdx.x * 128, n0 = blockIdx.y * 64;
    const int wm  = (wid & 3) * 32;
    const int wn  = (wid >> 2) * 32;

    float c[2][4][4];
    #pragma unroll
    for (int i = 0; i < 2; i++)
        #pragma unroll
        for (int j = 0; j < 4; j++)
            #pragma unroll
            for (int k = 0; k < 4; k++) c[i][j][k] = 0.f;

    const int kk = tid & 15;
    const int mb = tid >> 4;
    const int bn = tid & 63;
    const int bk = tid >> 6;

    for (int k0 = 0; k0 < K; k0 += 16) {
        int gk = k0 + kk;
        #pragma unroll
        for (int i = 0; i < 8; i++) {
            int mm = mb + i * 16;
            int gm = m0 + mm;
            float v = 0.f;
            if (gm < M && gk < K) {
                if (MODE == 1) {
                    if (gk < NFD)       v = x[(size_t)gm * NFD + gk];
                    else if (gk == NFD) v = (float)batch[gm];
                    else                v = agg[(size_t)gm * LL + (gk - NFD - 1)];
                } else if (MODE == 3) {
                    if (gk < NFD)       v = x[(size_t)gm * NFD + gk];
                    else                v = (float)batch[gm];
                } else {
                    float y = Y2[(size_t)gm * DD2 + gk];
                    v = fmaxf(fmaf(y, scale[gk], shift[gk]), 0.f);
                }
            }
            As[mm][kk] = f2tf(v);
        }
        #pragma unroll
        for (int i = 0; i < 4; i++) {
            int k = bk + i * 4;
            int gkb = k0 + k;
            int gn = n0 + bn;
            float v = (gkb < K && gn < Nc) ? B[(size_t)gkb * Nc + gn] : 0.f;
            Bs[bn][k] = f2tf(v);
        }
        __syncthreads();
        #pragma unroll
        for (int ks = 0; ks < 16; ks += 8) {
            unsigned a[2][4], b[4][2];
            #pragma unroll
            for (int mt = 0; mt < 2; mt++) {
                int rr = wm + mt * 16;
                a[mt][0] = As[rr + gid][ks + tg];
                a[mt][1] = As[rr + gid + 8][ks + tg];
                a[mt][2] = As[rr + gid][ks + tg + 4];
                a[mt][3] = As[rr + gid + 8][ks + tg + 4];
            }
            #pragma unroll
            for (int nt = 0; nt < 4; nt++) {
                int cc = wn + nt * 8;
                b[nt][0] = Bs[cc + gid][ks + tg];
                b[nt][1] = Bs[cc + gid][ks + tg + 4];
            }
            #pragma unroll
            for (int mt = 0; mt < 2; mt++)
                #pragma unroll
                for (int nt = 0; nt < 4; nt++)
                    mma_w(c[mt][nt], a[mt][0], a[mt][1], a[mt][2], a[mt][3],
                          b[nt][0], b[nt][1]);
        }
        __syncthreads();
    }
    #pragma unroll
    for (int mt = 0; mt < 2; mt++) {
        int r0 = m0 + wm + mt * 16 + gid;
        int r1 = r0 + 8;
        #pragma unroll
        for (int nt = 0; nt < 4; nt++) {
            int cb = n0 + wn + nt * 8 + 2 * tg;
            #pragma unroll
            for (int h = 0; h < 2; h++) {
                int col = cb + h;
                if (col >= Nc) continue;
                float bb = bias[col];
                if (r0 < M) {
                    float v = c[mt][nt][h] + bb;
                    if (relu_out) v = fmaxf(v, 0.f);
                    C[(size_t)r0 * Nc + col] = v;
                }
                if (r1 < M) {
                    float v = c[mt][nt][2 + h] + bb;
                    if (relu_out) v = fmaxf(v, 0.f);
                    C[(size_t)r1 * Nc + col] = v;
                }
            }
        }
    }
}

// ---------------- BN stats / finalize / CSR / gather ------------------------
__global__ void colstats_kernel(const float* __restrict__ Y, int M, int C, int rpb,
                                float* __restrict__ sum, float* __restrict__ sumsq)
{
    int r0 = blockIdx.x * rpb;
    int r1 = min(M, r0 + rpb);
    int c0 = threadIdx.x, c1 = threadIdx.x + 256;
    float s0 = 0, q0 = 0, s1 = 0, q1 = 0;
    for (int rr = r0; rr < r1; rr++) {
        const float* p = Y + (size_t)rr * C;
        if (c0 < C) { float v = p[c0]; s0 += v; q0 += v * v; }
        if (c1 < C) { float v = p[c1]; s1 += v; q1 += v * v; }
    }
    if (c0 < C) { atomicAdd(&sum[c0], s0); atomicAdd(&sumsq[c0], q0); }
    if (c1 < C) { atomicAdd(&sum[c1], s1); atomicAdd(&sumsq[c1], q1); }
}

__global__ void finalize_kernel(const float* __restrict__ sum, const float* __restrict__ sumsq,
                                int M, int C,
                                const float* __restrict__ gamma, const float* __restrict__ beta,
                                float* __restrict__ scale, float* __restrict__ shift)
{
    int c = blockIdx.x * blockDim.x + threadIdx.x;
    if (c < C) {
        float mu  = sum[c] / (float)M;
        float var = sumsq[c] / (float)M - mu * mu;
        float sc  = rsqrtf(var + BNEPS) * gamma[c];
        scale[c] = sc;
        shift[c] = beta[c] - mu * sc;
    }
}

__global__ void cnt_kernel(const int* __restrict__ col, int* __restrict__ cnt)
{
    int e = blockIdx.x * blockDim.x + threadIdx.x;
    if (e < NE) atomicAdd(&cnt[col[e]], 1);
}

__global__ void scan_kernel(const int* __restrict__ cnt,
                            int* __restrict__ off, int* __restrict__ cur)
{
    __shared__ int warpsum[32];
    __shared__ int base_s;
    int tid = threadIdx.x, lane = tid & 31, w = tid >> 5;
    if (tid == 0) base_s = 0;
    __syncthreads();
    for (int c0 = 0; c0 < NN; c0 += 1024) {
        int i = c0 + tid;
        int v = (i < NN) ? cnt[i] : 0;
        int inc = v;
        #pragma unroll
        for (int s = 1; s < 32; s <<= 1) {
            int t = __shfl_up_sync(0xffffffffu, inc, s);
            if (lane >= s) inc += t;
        }
        if (lane == 31) warpsum[w] = inc;
        __syncthreads();
        if (w == 0) {
            int ws = warpsum[lane];
            #pragma unroll
            for (int s = 1; s < 32; s <<= 1) {
                int t = __shfl_up_sync(0xffffffffu, ws, s);
                if (lane >= s) ws += t;
            }
            warpsum[lane] = ws;
        }
        __syncthreads();
        int base = base_s;
        int wexc = (w > 0) ? warpsum[w - 1] : 0;
        int excl = base + wexc + inc - v;
        if (i < NN) { off[i] = excl; cur[i] = excl; }
        int total = warpsum[31];
        __syncthreads();
        if (tid == 0) base_s = base + total;
        __syncthreads();
    }
    if (threadIdx.x == 0) off[NN] = base_s;
}

__global__ void bucket_kernel(const int* __restrict__ col,
                              int* __restrict__ cur, int* __restrict__ eid)
{
    int e = blockIdx.x * blockDim.x + threadIdx.x;
    if (e < NE) {
        int pos = atomicAdd(&cur[col[e]], 1);
        eid[pos] = e;
    }
}

__global__ void gather_kernel(const float* __restrict__ Y1,
                              const int* __restrict__ eid, const int* __restrict__ off,
                              const float* __restrict__ scale, const float* __restrict__ shift,
                              float* __restrict__ ssum)
{
    int n = blockIdx.x;
    int t = threadIdx.x;
    int s = off[n], e = off[n + 1];
    float sc = scale[t], sh = shift[t];
    float a0 = 0, a1 = 0, a2 = 0, a3 = 0;
    int j = s;
    for (; j + 4 <= e; j += 4) {
        int e0 = eid[j], e1 = eid[j + 1], e2 = eid[j + 2], e3 = eid[j + 3];
        float y0 = Y1[(size_t)e0 * LL + t];
        float y1 = Y1[(size_t)e1 * LL + t];
        float y2 = Y1[(size_t)e2 * LL + t];
        float y3 = Y1[(size_t)e3 * LL + t];
        a0 += fmaxf(fmaf(y0, sc, sh), 0.f);
        a1 += fmaxf(fmaf(y1, sc, sh), 0.f);
        a2 += fmaxf(fmaf(y2, sc, sh), 0.f);
        a3 += fmaxf(fmaf(y3, sc, sh), 0.f);
    }
    for (; j < e; j++) {
        float y = Y1[(size_t)eid[j] * LL + t];
        a0 += fmaxf(fmaf(y, sc, sh), 0.f);
    }
    float acc = (a0 + a1) + (a2 + a3);
    float inv = 1.f / (float)max(e - s, 1);
    ssum[(size_t)n * LL + t] = acc * inv;
}

extern "C" void kernel_launch(void* const* d_in, const int* in_sizes, int n_in,
                              void* d_out, int out_size)
{
    const float* x     = (const float*)d_in[0];
    const int*   eidx  = (const int*)  d_in[1];
    const float* eattr = (const float*)d_in[2];
    const int*   batch = (const int*)  d_in[4];
    const float* W1  = (const float*)d_in[5];
    const float* b1  = (const float*)d_in[6];
    const float* g1  = (const float*)d_in[7];
    const float* be1 = (const float*)d_in[8];
    const float* W2  = (const float*)d_in[9];
    const float* b2  = (const float*)d_in[10];
    const float* g2  = (const float*)d_in[11];
    const float* be2 = (const float*)d_in[12];
    const float* W3  = (const float*)d_in[13];
    const float* b3  = (const float*)d_in[14];
    float* out = (float*)d_out;

    const int* erow = eidx;
    const int* ecol = eidx + NE;

    void *pY1, *pY2, *pXW, *pss, *pcnt, *poff, *pcur, *peid, *pW1e;
    void *ps1, *pq1, *psc1, *psh1, *ps2, *pq2, *psc2, *psh2;
    cudaGetSymbolAddress(&pY1,  g_Y1);
    cudaGetSymbolAddress(&pY2,  g_Y2);
    cudaGetSymbolAddress(&pXW,  g_XW);
    cudaGetSymbolAddress(&pss,  g_ssum);
    cudaGetSymbolAddress(&pcnt, g_cnt);
    cudaGetSymbolAddress(&poff, g_off);
    cudaGetSymbolAddress(&pcur, g_cur);
    cudaGetSymbolAddress(&peid, g_eid);
    cudaGetSymbolAddress(&pW1e, g_W1e);
    cudaGetSymbolAddress(&ps1,  g_sum1);   cudaGetSymbolAddress(&pq1,  g_sumsq1);
    cudaGetSymbolAddress(&psc1, g_scale1); cudaGetSymbolAddress(&psh1, g_shift1);
    cudaGetSymbolAddress(&ps2,  g_sum2);   cudaGetSymbolAddress(&pq2,  g_sumsq2);
    cudaGetSymbolAddress(&psc2, g_scale2); cudaGetSymbolAddress(&psh2, g_shift2);

    cudaMemsetAsync(ps1,  0, LL  * sizeof(float), 0);
    cudaMemsetAsync(pq1,  0, LL  * sizeof(float), 0);
    cudaMemsetAsync(ps2,  0, DD2 * sizeof(float), 0);
    cudaMemsetAsync(pq2,  0, DD2 * sizeof(float), 0);
    cudaMemsetAsync(pcnt, 0, NN  * sizeof(int),   0);

    cudaFuncSetAttribute(edge_gemm, cudaFuncAttributeMaxDynamicSharedMemorySize, E_SMEM);

    // 0) prep W1e^T (tf32)
    prep_W1e<<<(LL * EFD + 255) / 256, 256>>>(W1, (uint32_t*)pW1e);

    // 1) XW = [x, batch] @ W1[0:129] + b1   (node-level part of edge MLP)
    gemm_tf32<3><<<dim3((NN + 127) / 128, LL / 64), 256>>>(
        NN, LL, KXW, W1, b1, (float*)pXW,
        x, batch, nullptr, nullptr, nullptr, nullptr, 0);

    // 2) edge GEMM (K=64) + XW gather-add + fused BN1 stats
    edge_gemm<<<NE / 128, 256, E_SMEM>>>(eattr, erow, (const uint32_t*)pW1e,
                                         (const float*)pXW, (float*)pY1,
                                         (float*)ps1, (float*)pq1);
    finalize_kernel<<<2, 256>>>((float*)ps1, (float*)pq1, NE, LL, g1, be1,
                                (float*)psc1, (float*)psh1);

    // 3) CSR build + gather-mean (BN+relu applied on the fly)
    cnt_kernel<<<NE / 256, 256>>>(ecol, (int*)pcnt);
    scan_kernel<<<1, 1024>>>((int*)pcnt, (int*)poff, (int*)pcur);
    bucket_kernel<<<NE / 256, 256>>>(ecol, (int*)pcur, (int*)peid);
    gather_kernel<<<NN, 256>>>((float*)pY1, (int*)peid, (int*)poff,
                               (float*)psc1, (float*)psh1, (float*)pss);

    // 4) node GEMM: Y2 = [x, batch, agg] @ W2 + b2
    gemm_tf32<1><<<dim3((NN + 127) / 128, (DD2 + 63) / 64), 256>>>(
        NN, DD2, DD2, W2, b2, (float*)pY2,
        x, batch, (float*)pss, nullptr, nullptr, nullptr, 0);

    // 5) BN2 stats
    colstats_kernel<<<(NN + 255) / 256, 256>>>((float*)pY2, NN, DD2, 256,
                                               (float*)ps2, (float*)pq2);
    finalize_kernel<<<2, 256>>>((float*)ps2, (float*)pq2, NN, DD2, g2, be2,
                                (float*)psc2, (float*)psh2);

    // 6) output GEMM: out = relu(relu(bn(Y2)) @ W3 + b3)
    gemm_tf32<2><<<dim3((NN + 127) / 128, NFD / 64), 256>>>(
        NN, NFD, DD2, W3, b3, out,
        nullptr, batch, nullptr, (float*)pY2, (float*)psc2, (float*)psh2, 1);
}

// round 7
// speedup vs baseline: 3.3619x; 1.0375x over previous
#include <cuda_runtime.h>
#include <cstdint>
#include <math.h>

#define NN   50000      // nodes
#define NE   800000     // edges
#define NFD  128        // node feature size
#define EFD  64         // edge feature size
#define LL   256        // layer size (mlp1 out)
#define DD1  193        // mlp1 input dim
#define DD2  385        // mlp2 dim
#define KXW  129        // x + batch part of mlp1 K
#define BNEPS 1e-5f

// ---------------- scratch (static device globals) ---------------------------
__device__ float    g_Y1[(size_t)NE * LL];     // edge MLP pre-BN output
__device__ float    g_Y2[(size_t)NN * DD2];    // node MLP pre-BN output
__device__ float    g_XW[(size_t)NN * LL];     // node part of edge MLP
__device__ float    g_ssum[(size_t)NN * LL];   // aggregated means
__device__ uint32_t g_W1e[LL * EFD];           // W1[129:193]^T as tf32, [n][k]
__device__ int      g_cnt[NN];
__device__ int      g_off[NN + 1];
__device__ int      g_cur[NN];
__device__ int      g_eid[NE];
__device__ float    g_sum1[LL],  g_sumsq1[LL],  g_scale1[LL],  g_shift1[LL];
__device__ float    g_sum2[DD2], g_sumsq2[DD2], g_scale2[DD2], g_shift2[DD2];

// ---------------- tf32 helpers ----------------------------------------------
__device__ __forceinline__ unsigned f2tf(float f) {
    unsigned r;
    asm("cvt.rna.tf32.f32 %0, %1;" : "=r"(r) : "f"(f));
    return r;
}
__device__ __forceinline__ void mma_w(float* c, unsigned a0, unsigned a1,
                                      unsigned a2, unsigned a3, unsigned b0, unsigned b1) {
    asm volatile(
        "mma.sync.aligned.m16n8k8.row.col.f32.tf32.tf32.f32 "
        "{%0,%1,%2,%3},{%4,%5,%6,%7},{%8,%9},{%0,%1,%2,%3};"
        : "+f"(c[0]), "+f"(c[1]), "+f"(c[2]), "+f"(c[3])
        : "r"(a0), "r"(a1), "r"(a2), "r"(a3), "r"(b0), "r"(b1));
}

// ---------------- prep: W1[129:193]^T -> tf32 [n][k] ------------------------
__global__ void prep_W1e(const float* __restrict__ W1, uint32_t* __restrict__ W1e)
{
    int idx = blockIdx.x * 256 + threadIdx.x;    // LL*EFD = 16384
    if (idx >= LL * EFD) return;
    int n = idx >> 6, k = idx & 63;
    W1e[idx] = f2tf(W1[(size_t)(KXW + k) * LL + n]);
}

// ---------------- edge GEMM (K=64) + XW gather-add + fused BN1 stats --------
#define ESA    0                         // As: eattr tf32 [128][68] = 34816
#define ESB    34816                     // Bs: W1e tile   [64][68]  = 17408
#define ESXW   52224                     // XWs: gathered  [128][68] = 34816
#define ESRIDX 87040                     // rIdx[128] = 512
#define ESSTAT 87552                     // sum[256], sq[256] = 2048
#define E_SMEM 89600

__global__ void __launch_bounds__(256) edge_gemm(
    const float* __restrict__ eattr, const int* __restrict__ erow,
    const uint32_t* __restrict__ W1e, const float* __restrict__ XW,
    float* __restrict__ Y1,
    float* __restrict__ gsum, float* __restrict__ gsq)
{
    extern __shared__ char smem[];
    uint32_t (*As)[68]  = (uint32_t(*)[68])(smem + ESA);
    uint32_t (*Bs)[68]  = (uint32_t(*)[68])(smem + ESB);
    float    (*XWs)[68] = (float(*)[68])   (smem + ESXW);
    int*   rIdx = (int*)  (smem + ESRIDX);
    float* sSum = (float*)(smem + ESSTAT);
    float* sSq  = (float*)(smem + ESSTAT + 1024);

    const int tid  = threadIdx.x;
    const int wid  = tid >> 5, lane = tid & 31;
    const int gid  = lane >> 2, tg = lane & 3;
    const int m0   = blockIdx.x * 128;
    const int wm   = (wid & 3) * 32;
    const int wn   = (wid >> 2) * 32;

    #pragma unroll
    for (int it = 0; it < 8; it++) {
        int idx = tid + it * 256;
        int row = idx >> 4, q = idx & 15;
        float4 v = *(const float4*)(eattr + (size_t)(m0 + row) * EFD + 4 * q);
        uint4 t; t.x = f2tf(v.x); t.y = f2tf(v.y); t.z = f2tf(v.z); t.w = f2tf(v.w);
        *(uint4*)&As[row][4 * q] = t;
    }
    if (tid < 128) rIdx[tid] = erow[m0 + tid];
    sSum[tid] = 0.f; sSq[tid] = 0.f;
    __syncthreads();

    for (int ct = 0; ct < 4; ct++) {
        const int n0 = ct * 64;
        #pragma unroll
        for (int it = 0; it < 4; it++) {
            int idx = tid + it * 256;
            int n = idx >> 4, q = idx & 15;
            uint4 t = *(const uint4*)(W1e + (size_t)(n0 + n) * EFD + 4 * q);
            *(uint4*)&Bs[n][4 * q] = t;
        }
        #pragma unroll
        for (int it = 0; it < 8; it++) {
            int idx = tid + it * 256;
            int row = idx >> 4, q = idx & 15;
            float4 v = *(const float4*)(XW + (size_t)rIdx[row] * LL + n0 + 4 * q);
            *(float4*)&XWs[row][4 * q] = v;
        }
        __syncthreads();

        float c[2][4][4];
        #pragma unroll
        for (int i = 0; i < 2; i++)
            #pragma unroll
            for (int j = 0; j < 4; j++)
                #pragma unroll
                for (int k = 0; k < 4; k++) c[i][j][k] = 0.f;

        #pragma unroll
        for (int ks = 0; ks < 64; ks += 8) {
            unsigned a[2][4], b[4][2];
            #pragma unroll
            for (int mt = 0; mt < 2; mt++) {
                int r = wm + mt * 16;
                a[mt][0] = As[r + gid][ks + tg];
                a[mt][1] = As[r + gid + 8][ks + tg];
                a[mt][2] = As[r + gid][ks + tg + 4];
                a[mt][3] = As[r + gid + 8][ks + tg + 4];
            }
            #pragma unroll
            for (int nt = 0; nt < 4; nt++) {
                int cc = wn + nt * 8;
                b[nt][0] = Bs[cc + gid][ks + tg];
                b[nt][1] = Bs[cc + gid][ks + tg + 4];
            }
            #pragma unroll
            for (int mt = 0; mt < 2; mt++)
                #pragma unroll
                for (int nt = 0; nt < 4; nt++)
                    mma_w(c[mt][nt], a[mt][0], a[mt][1], a[mt][2], a[mt][3],
                          b[nt][0], b[nt][1]);
        }

        float ls[8], lq[8];
        #pragma unroll
        for (int s = 0; s < 8; s++) { ls[s] = 0.f; lq[s] = 0.f; }
        #pragma unroll
        for (int mt = 0; mt < 2; mt++) {
            int r0 = wm + mt * 16 + gid;
            int r1 = r0 + 8;
            #pragma unroll
            for (int nt = 0; nt < 4; nt++) {
                int cb = wn + nt * 8 + 2 * tg;
                float v00 = c[mt][nt][0] + XWs[r0][cb];
                float v01 = c[mt][nt][1] + XWs[r0][cb + 1];
                float v10 = c[mt][nt][2] + XWs[r1][cb];
                float v11 = c[mt][nt][3] + XWs[r1][cb + 1];
                *(float2*)(Y1 + (size_t)(m0 + r0) * LL + n0 + cb) = make_float2(v00, v01);
                *(float2*)(Y1 + (size_t)(m0 + r1) * LL + n0 + cb) = make_float2(v10, v11);
                ls[nt * 2 + 0] += v00 + v10;  lq[nt * 2 + 0] += v00 * v00 + v10 * v10;
                ls[nt * 2 + 1] += v01 + v11;  lq[nt * 2 + 1] += v01 * v01 + v11 * v11;
            }
        }
        #pragma unroll
        for (int mask = 4; mask <= 16; mask <<= 1)
            #pragma unroll
            for (int s = 0; s < 8; s++) {
                ls[s] += __shfl_xor_sync(0xffffffffu, ls[s], mask);
                lq[s] += __shfl_xor_sync(0xffffffffu, lq[s], mask);
            }
        if (gid == 0) {
            #pragma unroll
            for (int nt = 0; nt < 4; nt++)
                #pragma unroll
                for (int h = 0; h < 2; h++) {
                    int col = n0 + wn + nt * 8 + 2 * tg + h;
                    atomicAdd(&sSum[col], ls[nt * 2 + h]);
                    atomicAdd(&sSq[col],  lq[nt * 2 + h]);
                }
        }
        __syncthreads();
    }
    atomicAdd(&gsum[tid], sSum[tid]);
    atomicAdd(&gsq[tid],  sSq[tid]);
}

// ---------------- generic warp-mma TF32 GEMM (modes 1,2,3) ------------------
//   MODE 1: node rows  = [x[m], batch[m], agg[m]]  + fused BN2 stats
//   MODE 2: relu(bn(Y2[m]))  (output)
//   MODE 3: xw rows    = [x[m], batch[m]]          (XW)
template<int MODE>
__global__ void __launch_bounds__(256) gemm_tf32(int M, int Nc, int K,
    const float* __restrict__ B, const float* __restrict__ bias,
    float* __restrict__ C,
    const float* __restrict__ x, const int* __restrict__ batch,
    const float* __restrict__ agg,
    const float* __restrict__ Y2,
    const float* __restrict__ scale, const float* __restrict__ shift,
    float* __restrict__ gsum, float* __restrict__ gsq,
    int relu_out)
{
    __shared__ unsigned As[128][17];
    __shared__ unsigned Bs[64][17];

    const int tid = threadIdx.x;
    const int wid = tid >> 5, lane = tid & 31;
    const int gid = lane >> 2, tg = lane & 3;
    const int m0  = blockIdx.x * 128, n0 = blockIdx.y * 64;
    const int wm  = (wid & 3) * 32;
    const int wn  = (wid >> 2) * 32;

    float c[2][4][4];
    #pragma unroll
    for (int i = 0; i < 2; i++)
        #pragma unroll
        for (int j = 0; j < 4; j++)
            #pragma unroll
            for (int k = 0; k < 4; k++) c[i][j][k] = 0.f;

    const int kk = tid & 15;
    const int mb = tid >> 4;
    const int bn = tid & 63;
    const int bk = tid >> 6;

    for (int k0 = 0; k0 < K; k0 += 16) {
        int gk = k0 + kk;
        #pragma unroll
        for (int i = 0; i < 8; i++) {
            int mm = mb + i * 16;
            int gm = m0 + mm;
            float v = 0.f;
            if (gm < M && gk < K) {
                if (MODE == 1) {
                    if (gk < NFD)       v = x[(size_t)gm * NFD + gk];
                    else if (gk == NFD) v = (float)batch[gm];
                    else                v = agg[(size_t)gm * LL + (gk - NFD - 1)];
                } else if (MODE == 3) {
                    if (gk < NFD)       v = x[(size_t)gm * NFD + gk];
                    else                v = (float)batch[gm];
                } else {
                    float y = Y2[(size_t)gm * DD2 + gk];
                    v = fmaxf(fmaf(y, scale[gk], shift[gk]), 0.f);
                }
            }
            As[mm][kk] = f2tf(v);
        }
        #pragma unroll
        for (int i = 0; i < 4; i++) {
            int k = bk + i * 4;
            int gkb = k0 + k;
            int gn = n0 + bn;
            float v = (gkb < K && gn < Nc) ? B[(size_t)gkb * Nc + gn] : 0.f;
            Bs[bn][k] = f2tf(v);
        }
        __syncthreads();
        #pragma unroll
        for (int ks = 0; ks < 16; ks += 8) {
            unsigned a[2][4], b[4][2];
            #pragma unroll
            for (int mt = 0; mt < 2; mt++) {
                int rr = wm + mt * 16;
                a[mt][0] = As[rr + gid][ks + tg];
                a[mt][1] = As[rr + gid + 8][ks + tg];
                a[mt][2] = As[rr + gid][ks + tg + 4];
                a[mt][3] = As[rr + gid + 8][ks + tg + 4];
            }
            #pragma unroll
            for (int nt = 0; nt < 4; nt++) {
                int cc = wn + nt * 8;
                b[nt][0] = Bs[cc + gid][ks + tg];
                b[nt][1] = Bs[cc + gid][ks + tg + 4];
            }
            #pragma unroll
            for (int mt = 0; mt < 2; mt++)
                #pragma unroll
                for (int nt = 0; nt < 4; nt++)
                    mma_w(c[mt][nt], a[mt][0], a[mt][1], a[mt][2], a[mt][3],
                          b[nt][0], b[nt][1]);
        }
        __syncthreads();
    }

    float ls[8], lq[8];
    if (MODE == 1) {
        #pragma unroll
        for (int s = 0; s < 8; s++) { ls[s] = 0.f; lq[s] = 0.f; }
    }
    #pragma unroll
    for (int mt = 0; mt < 2; mt++) {
        int r0 = m0 + wm + mt * 16 + gid;
        int r1 = r0 + 8;
        #pragma unroll
        for (int nt = 0; nt < 4; nt++) {
            int cb = wn + nt * 8 + 2 * tg;
            #pragma unroll
            for (int h = 0; h < 2; h++) {
                int col = n0 + cb + h;
                if (col >= Nc) continue;
                float bb = bias[col];
                if (r0 < M) {
                    float v = c[mt][nt][h] + bb;
                    if (relu_out) v = fmaxf(v, 0.f);
                    C[(size_t)r0 * Nc + col] = v;
                    if (MODE == 1) { ls[nt * 2 + h] += v; lq[nt * 2 + h] += v * v; }
                }
                if (r1 < M) {
                    float v = c[mt][nt][2 + h] + bb;
                    if (relu_out) v = fmaxf(v, 0.f);
                    C[(size_t)r1 * Nc + col] = v;
                    if (MODE == 1) { ls[nt * 2 + h] += v; lq[nt * 2 + h] += v * v; }
                }
            }
        }
    }
    if (MODE == 1) {
        #pragma unroll
        for (int mask = 4; mask <= 16; mask <<= 1)
            #pragma unroll
            for (int s = 0; s < 8; s++) {
                ls[s] += __shfl_xor_sync(0xffffffffu, ls[s], mask);
                lq[s] += __shfl_xor_sync(0xffffffffu, lq[s], mask);
            }
        if (gid == 0) {
            #pragma unroll
            for (int nt = 0; nt < 4; nt++)
                #pragma unroll
                for (int h = 0; h < 2; h++) {
                    int col = n0 + wn + nt * 8 + 2 * tg + h;
                    if (col < Nc) {
                        atomicAdd(&gsum[col], ls[nt * 2 + h]);
                        atomicAdd(&gsq[col],  lq[nt * 2 + h]);
                    }
                }
        }
    }
}

// ---------------- BN finalize / CSR / gather --------------------------------
__global__ void finalize_kernel(const float* __restrict__ sum, const float* __restrict__ sumsq,
                                int M, int C,
                                const float* __restrict__ gamma, const float* __restrict__ beta,
                                float* __restrict__ scale, float* __restrict__ shift)
{
    int c = blockIdx.x * blockDim.x + threadIdx.x;
    if (c < C) {
        float mu  = sum[c] / (float)M;
        float var = sumsq[c] / (float)M - mu * mu;
        float sc  = rsqrtf(var + BNEPS) * gamma[c];
        scale[c] = sc;
        shift[c] = beta[c] - mu * sc;
    }
}

__global__ void cnt_kernel(const int* __restrict__ col, int* __restrict__ cnt)
{
    int e = blockIdx.x * blockDim.x + threadIdx.x;
    if (e < NE) atomicAdd(&cnt[col[e]], 1);
}

__global__ void scan_kernel(const int* __restrict__ cnt,
                            int* __restrict__ off, int* __restrict__ cur)
{
    __shared__ int warpsum[32];
    __shared__ int base_s;
    int tid = threadIdx.x, lane = tid & 31, w = tid >> 5;
    if (tid == 0) base_s = 0;
    __syncthreads();
    for (int c0 = 0; c0 < NN; c0 += 1024) {
        int i = c0 + tid;
        int v = (i < NN) ? cnt[i] : 0;
        int inc = v;
        #pragma unroll
        for (int s = 1; s < 32; s <<= 1) {
            int t = __shfl_up_sync(0xffffffffu, inc, s);
            if (lane >= s) inc += t;
        }
        if (lane == 31) warpsum[w] = inc;
        __syncthreads();
        if (w == 0) {
            int ws = warpsum[lane];
            #pragma unroll
            for (int s = 1; s < 32; s <<= 1) {
                int t = __shfl_up_sync(0xffffffffu, ws, s);
                if (lane >= s) ws += t;
            }
            warpsum[lane] = ws;
        }
        __syncthreads();
        int base = base_s;
        int wexc = (w > 0) ? warpsum[w - 1] : 0;
        int excl = base + wexc + inc - v;
        if (i < NN) { off[i] = excl; cur[i] = excl; }
        int total = warpsum[31];
        __syncthreads();
        if (tid == 0) base_s = base + total;
        __syncthreads();
    }
    if (threadIdx.x == 0) off[NN] = base_s;
}

__global__ void bucket_kernel(const int* __restrict__ col,
                              int* __restrict__ cur, int* __restrict__ eid)
{
    int e = blockIdx.x * blockDim.x + threadIdx.x;
    if (e < NE) {
        int pos = atomicAdd(&cur[col[e]], 1);
        eid[pos] = e;
    }
}

// per-node gather-sum of relu(bn(Y1)) rows, vectorized float4, then mean
__global__ void __launch_bounds__(256) gather_kernel(
    const float* __restrict__ Y1,
    const int* __restrict__ eid, const int* __restrict__ off,
    const float* __restrict__ scale, const float* __restrict__ shift,
    float* __restrict__ ssum)
{
    __shared__ float4 part[4][64];
    const int n   = blockIdx.x;
    const int sub = threadIdx.x >> 6;          // 0..3 (edge sub-lane)
    const int cgi = threadIdx.x & 63;          // col group index
    const int cg  = cgi << 2;                  // col base (0,4,..,252)
    const int s = off[n], e = off[n + 1];

    float4 sc = *(const float4*)(scale + cg);
    float4 sh = *(const float4*)(shift + cg);
    float4 acc = make_float4(0.f, 0.f, 0.f, 0.f);

    for (int j = s + sub; j < e; j += 4) {
        int ej = eid[j];
        float4 y = *(const float4*)(Y1 + (size_t)ej * LL + cg);
        acc.x += fmaxf(fmaf(y.x, sc.x, sh.x), 0.f);
        acc.y += fmaxf(fmaf(y.y, sc.y, sh.y), 0.f);
        acc.z += fmaxf(fmaf(y.z, sc.z, sh.z), 0.f);
        acc.w += fmaxf(fmaf(y.w, sc.w, sh.w), 0.f);
    }
    part[sub][cgi] = acc;
    __syncthreads();
    if (threadIdx.x < 64) {
        float4 a0 = part[0][threadIdx.x], a1 = part[1][threadIdx.x];
        float4 a2 = part[2][threadIdx.x], a3 = part[3][threadIdx.x];
        float inv = 1.f / (float)max(e - s, 1);
        float4 o;
        o.x = (a0.x + a1.x + a2.x + a3.x) * inv;
        o.y = (a0.y + a1.y + a2.y + a3.y) * inv;
        o.z = (a0.z + a1.z + a2.z + a3.z) * inv;
        o.w = (a0.w + a1.w + a2.w + a3.w) * inv;
        *(float4*)(ssum + (size_t)n * LL + (threadIdx.x << 2)) = o;
    }
}

extern "C" void kernel_launch(void* const* d_in, const int* in_sizes, int n_in,
                              void* d_out, int out_size)
{
    const float* x     = (const float*)d_in[0];
    const int*   eidx  = (const int*)  d_in[1];
    const float* eattr = (const float*)d_in[2];
    const int*   batch = (const int*)  d_in[4];
    const float* W1  = (const float*)d_in[5];
    const float* b1  = (const float*)d_in[6];
    const float* g1  = (const float*)d_in[7];
    const float* be1 = (const float*)d_in[8];
    const float* W2  = (const float*)d_in[9];
    const float* b2  = (const float*)d_in[10];
    const float* g2  = (const float*)d_in[11];
    const float* be2 = (const float*)d_in[12];
    const float* W3  = (const float*)d_in[13];
    const float* b3  = (const float*)d_in[14];
    float* out = (float*)d_out;

    const int* erow = eidx;
    const int* ecol = eidx + NE;

    void *pY1, *pY2, *pXW, *pss, *pcnt, *poff, *pcur, *peid, *pW1e;
    void *ps1, *pq1, *psc1, *psh1, *ps2, *pq2, *psc2, *psh2;
    cudaGetSymbolAddress(&pY1,  g_Y1);
    cudaGetSymbolAddress(&pY2,  g_Y2);
    cudaGetSymbolAddress(&pXW,  g_XW);
    cudaGetSymbolAddress(&pss,  g_ssum);
    cudaGetSymbolAddress(&pcnt, g_cnt);
    cudaGetSymbolAddress(&poff, g_off);
    cudaGetSymbolAddress(&pcur, g_cur);
    cudaGetSymbolAddress(&peid, g_eid);
    cudaGetSymbolAddress(&pW1e, g_W1e);
    cudaGetSymbolAddress(&ps1,  g_sum1);   cudaGetSymbolAddress(&pq1,  g_sumsq1);
    cudaGetSymbolAddress(&psc1, g_scale1); cudaGetSymbolAddress(&psh1, g_shift1);
    cudaGetSymbolAddress(&ps2,  g_sum2);   cudaGetSymbolAddress(&pq2,  g_sumsq2);
    cudaGetSymbolAddress(&psc2, g_scale2); cudaGetSymbolAddress(&psh2, g_shift2);

    // persistent side stream + events (host objects; created once)
    static cudaStream_t s2 = nullptr;
    static cudaEvent_t ev1 = nullptr, ev2 = nullptr;
    if (!s2) {
        cudaStreamCreateWithFlags(&s2, cudaStreamNonBlocking);
        cudaEventCreateWithFlags(&ev1, cudaEventDisableTiming);
        cudaEventCreateWithFlags(&ev2, cudaEventDisableTiming);
    }

    cudaMemsetAsync(ps1,  0, LL  * sizeof(float), 0);
    cudaMemsetAsync(pq1,  0, LL  * sizeof(float), 0);
    cudaMemsetAsync(ps2,  0, DD2 * sizeof(float), 0);
    cudaMemsetAsync(pq2,  0, DD2 * sizeof(float), 0);
    cudaMemsetAsync(pcnt, 0, NN  * sizeof(int),   0);

    cudaFuncSetAttribute(edge_gemm, cudaFuncAttributeMaxDynamicSharedMemorySize, E_SMEM);

    // ---- fork: CSR build on side stream (depends only on ecol + cnt memset)
    cudaEventRecord(ev1, 0);
    cudaStreamWaitEvent(s2, ev1, 0);
    cnt_kernel<<<NE / 256, 256, 0, s2>>>(ecol, (int*)pcnt);
    scan_kernel<<<1, 1024, 0, s2>>>((int*)pcnt, (int*)poff, (int*)pcur);
    bucket_kernel<<<NE / 256, 256, 0, s2>>>(ecol, (int*)pcur, (int*)peid);
    cudaEventRecord(ev2, s2);

    // ---- main chain on stream 0
    prep_W1e<<<(LL * EFD + 255) / 256, 256>>>(W1, (uint32_t*)pW1e);

    gemm_tf32<3><<<dim3((NN + 127) / 128, LL / 64), 256>>>(
        NN, LL, KXW, W1, b1, (float*)pXW,
        x, batch, nullptr, nullptr, nullptr, nullptr, nullptr, nullptr, 0);

    edge_gemm<<<NE / 128, 256, E_SMEM>>>(eattr, erow, (const uint32_t*)pW1e,
                                         (const float*)pXW, (float*)pY1,
                                         (float*)ps1, (float*)pq1);
    finalize_kernel<<<2, 256>>>((float*)ps1, (float*)pq1, NE, LL, g1, be1,
                                (float*)psc1, (float*)psh1);

    // ---- join: gather needs CSR + Y1 + scale/shift
    cudaStreamWaitEvent(0, ev2, 0);
    gather_kernel<<<NN, 256>>>((float*)pY1, (int*)peid, (int*)poff,
                               (float*)psc1, (float*)psh1, (float*)pss);

    // node GEMM with fused BN2 stats
    gemm_tf32<1><<<dim3((NN + 127) / 128, (DD2 + 63) / 64), 256>>>(
        NN, DD2, DD2, W2, b2, (float*)pY2,
        x, batch, (float*)pss, nullptr, nullptr, nullptr,
        (float*)ps2, (float*)pq2, 0);

    finalize_kernel<<<2, 256>>>((float*)ps2, (float*)pq2, NN, DD2, g2, be2,
                                (float*)psc2, (float*)psh2);

    gemm_tf32<2><<<dim3((NN + 127) / 128, NFD / 64), 256>>>(
        NN, NFD, DD2, W3, b3, out,
        nullptr, batch, nullptr, (float*)pY2, (float*)psc2, (float*)psh2,
        nullptr, nullptr, 1);
}

// round 8
// speedup vs baseline: 3.6723x; 1.0923x over previous
#include <cuda_runtime.h>
#include <cuda_fp16.h>
#include <cstdint>
#include <math.h>

#define NN   50000      // nodes
#define NE   800000     // edges
#define NFD  128        // node feature size
#define EFD  64         // edge feature size
#define LL   256        // layer size (mlp1 out)
#define DD1  193        // mlp1 input dim
#define DD2  385        // mlp2 dim
#define KXW  129        // x + batch part of mlp1 K
#define BNEPS 1e-5f

// ---------------- scratch (static device globals) ---------------------------
__device__ __half   g_Y1[(size_t)NE * LL];     // edge MLP pre-BN output (fp16)
__device__ float    g_Y2[(size_t)NN * DD2];    // node MLP pre-BN output
__device__ __half   g_XW[(size_t)NN * LL];     // node part of edge MLP (fp16)
__device__ float    g_ssum[(size_t)NN * LL];   // aggregated means
__device__ uint32_t g_W1e[LL * EFD];           // W1[129:193]^T as tf32, [n][k]
__device__ int      g_cnt[NN];
__device__ int      g_off[NN + 1];
__device__ int      g_cur[NN];
__device__ int      g_eid[NE];
__device__ float    g_sum1[LL],  g_sumsq1[LL],  g_scale1[LL],  g_shift1[LL];
__device__ float    g_sum2[DD2], g_sumsq2[DD2], g_scale2[DD2], g_shift2[DD2];

// ---------------- tf32 helpers ----------------------------------------------
__device__ __forceinline__ unsigned f2tf(float f) {
    unsigned r;
    asm("cvt.rna.tf32.f32 %0, %1;" : "=r"(r) : "f"(f));
    return r;
}
__device__ __forceinline__ void mma_w(float* c, unsigned a0, unsigned a1,
                                      unsigned a2, unsigned a3, unsigned b0, unsigned b1) {
    asm volatile(
        "mma.sync.aligned.m16n8k8.row.col.f32.tf32.tf32.f32 "
        "{%0,%1,%2,%3},{%4,%5,%6,%7},{%8,%9},{%0,%1,%2,%3};"
        : "+f"(c[0]), "+f"(c[1]), "+f"(c[2]), "+f"(c[3])
        : "r"(a0), "r"(a1), "r"(a2), "r"(a3), "r"(b0), "r"(b1));
}

// ---------------- prep: W1[129:193]^T -> tf32 [n][k] ------------------------
__global__ void prep_W1e(const float* __restrict__ W1, uint32_t* __restrict__ W1e)
{
    int idx = blockIdx.x * 256 + threadIdx.x;    // LL*EFD = 16384
    if (idx >= LL * EFD) return;
    int n = idx >> 6, k = idx & 63;
    W1e[idx] = f2tf(W1[(size_t)(KXW + k) * LL + n]);
}

// ---------------- edge GEMM (K=64) + XW gather-add + fused BN1 stats --------
#define ESA    0                         // As: eattr tf32 [128][68] = 34816
#define ESB    34816                     // Bs: W1e tile   [64][68]  = 17408
#define ESXW   52224                     // XWs: gathered  [128][68] = 34816
#define ESRIDX 87040                     // rIdx[128] = 512
#define ESSTAT 87552                     // sum[256], sq[256] = 2048
#define E_SMEM 89600

__global__ void __launch_bounds__(256) edge_gemm(
    const float* __restrict__ eattr, const int* __restrict__ erow,
    const uint32_t* __restrict__ W1e, const __half* __restrict__ XW,
    __half* __restrict__ Y1,
    float* __restrict__ gsum, float* __restrict__ gsq)
{
    extern __shared__ char smem[];
    uint32_t (*As)[68]  = (uint32_t(*)[68])(smem + ESA);
    uint32_t (*Bs)[68]  = (uint32_t(*)[68])(smem + ESB);
    float    (*XWs)[68] = (float(*)[68])   (smem + ESXW);
    int*   rIdx = (int*)  (smem + ESRIDX);
    float* sSum = (float*)(smem + ESSTAT);
    float* sSq  = (float*)(smem + ESSTAT + 1024);

    const int tid  = threadIdx.x;
    const int wid  = tid >> 5, lane = tid & 31;
    const int gid  = lane >> 2, tg = lane & 3;
    const int m0   = blockIdx.x * 128;
    const int wm   = (wid & 3) * 32;
    const int wn   = (wid >> 2) * 32;

    #pragma unroll
    for (int it = 0; it < 8; it++) {
        int idx = tid + it * 256;
        int row = idx >> 4, q = idx & 15;
        float4 v = *(const float4*)(eattr + (size_t)(m0 + row) * EFD + 4 * q);
        uint4 t; t.x = f2tf(v.x); t.y = f2tf(v.y); t.z = f2tf(v.z); t.w = f2tf(v.w);
        *(uint4*)&As[row][4 * q] = t;
    }
    if (tid < 128) rIdx[tid] = erow[m0 + tid];
    sSum[tid] = 0.f; sSq[tid] = 0.f;
    __syncthreads();

    for (int ct = 0; ct < 4; ct++) {
        const int n0 = ct * 64;
        #pragma unroll
        for (int it = 0; it < 4; it++) {
            int idx = tid + it * 256;
            int n = idx >> 4, q = idx & 15;
            uint4 t = *(const uint4*)(W1e + (size_t)(n0 + n) * EFD + 4 * q);
            *(uint4*)&Bs[n][4 * q] = t;
        }
        // stage XW tile [128 x 64] (fp16 -> fp32 in smem)
        #pragma unroll
        for (int it = 0; it < 8; it++) {
            int idx = tid + it * 256;
            int row = idx >> 4, q = idx & 15;
            uint2 raw = *(const uint2*)(XW + (size_t)rIdx[row] * LL + n0 + 4 * q);
            __half2* ph = (__half2*)&raw;
            float2 f0 = __half22float2(ph[0]);
            float2 f1 = __half22float2(ph[1]);
            *(float4*)&XWs[row][4 * q] = make_float4(f0.x, f0.y, f1.x, f1.y);
        }
        __syncthreads();

        float c[2][4][4];
        #pragma unroll
        for (int i = 0; i < 2; i++)
            #pragma unroll
            for (int j = 0; j < 4; j++)
                #pragma unroll
                for (int k = 0; k < 4; k++) c[i][j][k] = 0.f;

        #pragma unroll
        for (int ks = 0; ks < 64; ks += 8) {
            unsigned a[2][4], b[4][2];
            #pragma unroll
            for (int mt = 0; mt < 2; mt++) {
                int r = wm + mt * 16;
                a[mt][0] = As[r + gid][ks + tg];
                a[mt][1] = As[r + gid + 8][ks + tg];
                a[mt][2] = As[r + gid][ks + tg + 4];
                a[mt][3] = As[r + gid + 8][ks + tg + 4];
            }
            #pragma unroll
            for (int nt = 0; nt < 4; nt++) {
                int cc = wn + nt * 8;
                b[nt][0] = Bs[cc + gid][ks + tg];
                b[nt][1] = Bs[cc + gid][ks + tg + 4];
            }
            #pragma unroll
            for (int mt = 0; mt < 2; mt++)
                #pragma unroll
                for (int nt = 0; nt < 4; nt++)
                    mma_w(c[mt][nt], a[mt][0], a[mt][1], a[mt][2], a[mt][3],
                          b[nt][0], b[nt][1]);
        }

        float ls[8], lq[8];
        #pragma unroll
        for (int s = 0; s < 8; s++) { ls[s] = 0.f; lq[s] = 0.f; }
        #pragma unroll
        for (int mt = 0; mt < 2; mt++) {
            int r0 = wm + mt * 16 + gid;
            int r1 = r0 + 8;
            #pragma unroll
            for (int nt = 0; nt < 4; nt++) {
                int cb = wn + nt * 8 + 2 * tg;
                float v00 = c[mt][nt][0] + XWs[r0][cb];
                float v01 = c[mt][nt][1] + XWs[r0][cb + 1];
                float v10 = c[mt][nt][2] + XWs[r1][cb];
                float v11 = c[mt][nt][3] + XWs[r1][cb + 1];
                *(__half2*)(Y1 + (size_t)(m0 + r0) * LL + n0 + cb) = __floats2half2_rn(v00, v01);
                *(__half2*)(Y1 + (size_t)(m0 + r1) * LL + n0 + cb) = __floats2half2_rn(v10, v11);
                ls[nt * 2 + 0] += v00 + v10;  lq[nt * 2 + 0] += v00 * v00 + v10 * v10;
                ls[nt * 2 + 1] += v01 + v11;  lq[nt * 2 + 1] += v01 * v01 + v11 * v11;
            }
        }
        #pragma unroll
        for (int mask = 4; mask <= 16; mask <<= 1)
            #pragma unroll
            for (int s = 0; s < 8; s++) {
                ls[s] += __shfl_xor_sync(0xffffffffu, ls[s], mask);
                lq[s] += __shfl_xor_sync(0xffffffffu, lq[s], mask);
            }
        if (gid == 0) {
            #pragma unroll
            for (int nt = 0; nt < 4; nt++)
                #pragma unroll
                for (int h = 0; h < 2; h++) {
                    int col = n0 + wn + nt * 8 + 2 * tg + h;
                    atomicAdd(&sSum[col], ls[nt * 2 + h]);
                    atomicAdd(&sSq[col],  lq[nt * 2 + h]);
                }
        }
        __syncthreads();
    }
    atomicAdd(&gsum[tid], sSum[tid]);
    atomicAdd(&gsq[tid],  sSq[tid]);
}

// ---------------- generic warp-mma TF32 GEMM (modes 1,2,3) ------------------
//   MODE 1: node rows  = [x[m], batch[m], agg[m]]  + fused BN2 stats
//   MODE 2: relu(bn(Y2[m]))  (output)
//   MODE 3: xw rows    = [x[m], batch[m]]          (XW, fp16 output)
template<int MODE>
__global__ void __launch_bounds__(256) gemm_tf32(int M, int Nc, int K,
    const float* __restrict__ B, const float* __restrict__ bias,
    float* __restrict__ C, __half* __restrict__ Ch,
    const float* __restrict__ x, const int* __restrict__ batch,
    const float* __restrict__ agg,
    const float* __restrict__ Y2,
    const float* __restrict__ scale, const float* __restrict__ shift,
    float* __restrict__ gsum, float* __restrict__ gsq,
    int relu_out)
{
    __shared__ unsigned As[128][17];
    __shared__ unsigned Bs[64][17];

    const int tid = threadIdx.x;
    const int wid = tid >> 5, lane = tid & 31;
    const int gid = lane >> 2, tg = lane & 3;
    const int m0  = blockIdx.x * 128, n0 = blockIdx.y * 64;
    const int wm  = (wid & 3) * 32;
    const int wn  = (wid >> 2) * 32;

    float c[2][4][4];
    #pragma unroll
    for (int i = 0; i < 2; i++)
        #pragma unroll
        for (int j = 0; j < 4; j++)
            #pragma unroll
            for (int k = 0; k < 4; k++) c[i][j][k] = 0.f;

    const int kk = tid & 15;
    const int mb = tid >> 4;
    const int bn = tid & 63;
    const int bk = tid >> 6;

    for (int k0 = 0; k0 < K; k0 += 16) {
        int gk = k0 + kk;
        #pragma unroll
        for (int i = 0; i < 8; i++) {
            int mm = mb + i * 16;
            int gm = m0 + mm;
            float v = 0.f;
            if (gm < M && gk < K) {
                if (MODE == 1) {
                    if (gk < NFD)       v = x[(size_t)gm * NFD + gk];
                    else if (gk == NFD) v = (float)batch[gm];
                    else                v = agg[(size_t)gm * LL + (gk - NFD - 1)];
                } else if (MODE == 3) {
                    if (gk < NFD)       v = x[(size_t)gm * NFD + gk];
                    else                v = (float)batch[gm];
                } else {
                    float y = Y2[(size_t)gm * DD2 + gk];
                    v = fmaxf(fmaf(y, scale[gk], shift[gk]), 0.f);
                }
            }
            As[mm][kk] = f2tf(v);
        }
        #pragma unroll
        for (int i = 0; i < 4; i++) {
            int k = bk + i * 4;
            int gkb = k0 + k;
            int gn = n0 + bn;
            float v = (gkb < K && gn < Nc) ? B[(size_t)gkb * Nc + gn] : 0.f;
            Bs[bn][k] = f2tf(v);
        }
        __syncthreads();
        #pragma unroll
        for (int ks = 0; ks < 16; ks += 8) {
            unsigned a[2][4], b[4][2];
            #pragma unroll
            for (int mt = 0; mt < 2; mt++) {
                int rr = wm + mt * 16;
                a[mt][0] = As[rr + gid][ks + tg];
                a[mt][1] = As[rr + gid + 8][ks + tg];
                a[mt][2] = As[rr + gid][ks + tg + 4];
                a[mt][3] = As[rr + gid + 8][ks + tg + 4];
            }
            #pragma unroll
            for (int nt = 0; nt < 4; nt++) {
                int cc = wn + nt * 8;
                b[nt][0] = Bs[cc + gid][ks + tg];
                b[nt][1] = Bs[cc + gid][ks + tg + 4];
            }
            #pragma unroll
            for (int mt = 0; mt < 2; mt++)
                #pragma unroll
                for (int nt = 0; nt < 4; nt++)
                    mma_w(c[mt][nt], a[mt][0], a[mt][1], a[mt][2], a[mt][3],
                          b[nt][0], b[nt][1]);
        }
        __syncthreads();
    }

    float ls[8], lq[8];
    if (MODE == 1) {
        #pragma unroll
        for (int s = 0; s < 8; s++) { ls[s] = 0.f; lq[s] = 0.f; }
    }
    #pragma unroll
    for (int mt = 0; mt < 2; mt++) {
        int r0 = m0 + wm + mt * 16 + gid;
        int r1 = r0 + 8;
        #pragma unroll
        for (int nt = 0; nt < 4; nt++) {
            int cb = wn + nt * 8 + 2 * tg;
            if (MODE == 3) {
                // fp16 output, Nc==256 -> always in range
                float b0 = bias[n0 + cb], b1 = bias[n0 + cb + 1];
                if (r0 < M)
                    *(__half2*)(Ch + (size_t)r0 * Nc + n0 + cb) =
                        __floats2half2_rn(c[mt][nt][0] + b0, c[mt][nt][1] + b1);
                if (r1 < M)
                    *(__half2*)(Ch + (size_t)r1 * Nc + n0 + cb) =
                        __floats2half2_rn(c[mt][nt][2] + b0, c[mt][nt][3] + b1);
            } else {
                #pragma unroll
                for (int h = 0; h < 2; h++) {
                    int col = n0 + cb + h;
                    if (col >= Nc) continue;
                    float bb = bias[col];
                    if (r0 < M) {
                        float v = c[mt][nt][h] + bb;
                        if (relu_out) v = fmaxf(v, 0.f);
                        C[(size_t)r0 * Nc + col] = v;
                        if (MODE == 1) { ls[nt * 2 + h] += v; lq[nt * 2 + h] += v * v; }
                    }
                    if (r1 < M) {
                        float v = c[mt][nt][2 + h] + bb;
                        if (relu_out) v = fmaxf(v, 0.f);
                        C[(size_t)r1 * Nc + col] = v;
                        if (MODE == 1) { ls[nt * 2 + h] += v; lq[nt * 2 + h] += v * v; }
                    }
                }
            }
        }
    }
    if (MODE == 1) {
        #pragma unroll
        for (int mask = 4; mask <= 16; mask <<= 1)
            #pragma unroll
            for (int s = 0; s < 8; s++) {
                ls[s] += __shfl_xor_sync(0xffffffffu, ls[s], mask);
                lq[s] += __shfl_xor_sync(0xffffffffu, lq[s], mask);
            }
        if (gid == 0) {
            #pragma unroll
            for (int nt = 0; nt < 4; nt++)
                #pragma unroll
                for (int h = 0; h < 2; h++) {
                    int col = n0 + wn + nt * 8 + 2 * tg + h;
                    if (col < Nc) {
                        atomicAdd(&gsum[col], ls[nt * 2 + h]);
                        atomicAdd(&gsq[col],  lq[nt * 2 + h]);
                    }
                }
        }
    }
}

// ---------------- BN finalize / CSR / gather --------------------------------
__global__ void finalize_kernel(const float* __restrict__ sum, const float* __restrict__ sumsq,
                                int M, int C,
                                const float* __restrict__ gamma, const float* __restrict__ beta,
                                float* __restrict__ scale, float* __restrict__ shift)
{
    int c = blockIdx.x * blockDim.x + threadIdx.x;
    if (c < C) {
        float mu  = sum[c] / (float)M;
        float var = sumsq[c] / (float)M - mu * mu;
        float sc  = rsqrtf(var + BNEPS) * gamma[c];
        scale[c] = sc;
        shift[c] = beta[c] - mu * sc;
    }
}

__global__ void cnt_kernel(const int* __restrict__ col, int* __restrict__ cnt)
{
    int e = blockIdx.x * blockDim.x + threadIdx.x;
    if (e < NE) atomicAdd(&cnt[col[e]], 1);
}

__global__ void scan_kernel(const int* __restrict__ cnt,
                            int* __restrict__ off, int* __restrict__ cur)
{
    __shared__ int warpsum[32];
    __shared__ int base_s;
    int tid = threadIdx.x, lane = tid & 31, w = tid >> 5;
    if (tid == 0) base_s = 0;
    __syncthreads();
    for (int c0 = 0; c0 < NN; c0 += 1024) {
        int i = c0 + tid;
        int v = (i < NN) ? cnt[i] : 0;
        int inc = v;
        #pragma unroll
        for (int s = 1; s < 32; s <<= 1) {
            int t = __shfl_up_sync(0xffffffffu, inc, s);
            if (lane >= s) inc += t;
        }
        if (lane == 31) warpsum[w] = inc;
        __syncthreads();
        if (w == 0) {
            int ws = warpsum[lane];
            #pragma unroll
            for (int s = 1; s < 32; s <<= 1) {
                int t = __shfl_up_sync(0xffffffffu, ws, s);
                if (lane >= s) ws += t;
            }
            warpsum[lane] = ws;
        }
        __syncthreads();
        int base = base_s;
        int wexc = (w > 0) ? warpsum[w - 1] : 0;
        int excl = base + wexc + inc - v;
        if (i < NN) { off[i] = excl; cur[i] = excl; }
        int total = warpsum[31];
        __syncthreads();
        if (tid == 0) base_s = base + total;
        __syncthreads();
    }
    if (threadIdx.x == 0) off[NN] = base_s;
}

__global__ void bucket_kernel(const int* __restrict__ col,
                              int* __restrict__ cur, int* __restrict__ eid)
{
    int e = blockIdx.x * blockDim.x + threadIdx.x;
    if (e < NE) {
        int pos = atomicAdd(&cur[col[e]], 1);
        eid[pos] = e;
    }
}

// per-node gather-sum of relu(bn(Y1)) rows (fp16 Y1), then mean
__global__ void __launch_bounds__(256) gather_kernel(
    const __half* __restrict__ Y1,
    const int* __restrict__ eid, const int* __restrict__ off,
    const float* __restrict__ scale, const float* __restrict__ shift,
    float* __restrict__ ssum)
{
    __shared__ float4 part[4][64];
    const int n   = blockIdx.x;
    const int sub = threadIdx.x >> 6;          // 0..3 (edge sub-lane)
    const int cgi = threadIdx.x & 63;          // col group index
    const int cg  = cgi << 2;                  // col base (0,4,..,252)
    const int s = off[n], e = off[n + 1];

    float4 sc = *(const float4*)(scale + cg);
    float4 sh = *(const float4*)(shift + cg);
    float4 acc = make_float4(0.f, 0.f, 0.f, 0.f);

    for (int j = s + sub; j < e; j += 4) {
        int ej = eid[j];
        uint2 raw = *(const uint2*)(Y1 + (size_t)ej * LL + cg);
        __half2* ph = (__half2*)&raw;
        float2 y0 = __half22float2(ph[0]);
        float2 y1 = __half22float2(ph[1]);
        acc.x += fmaxf(fmaf(y0.x, sc.x, sh.x), 0.f);
        acc.y += fmaxf(fmaf(y0.y, sc.y, sh.y), 0.f);
        acc.z += fmaxf(fmaf(y1.x, sc.z, sh.z), 0.f);
        acc.w += fmaxf(fmaf(y1.y, sc.w, sh.w), 0.f);
    }
    part[sub][cgi] = acc;
    __syncthreads();
    if (threadIdx.x < 64) {
        float4 a0 = part[0][threadIdx.x], a1 = part[1][threadIdx.x];
        float4 a2 = part[2][threadIdx.x], a3 = part[3][threadIdx.x];
        float inv = 1.f / (float)max(e - s, 1);
        float4 o;
        o.x = (a0.x + a1.x + a2.x + a3.x) * inv;
        o.y = (a0.y + a1.y + a2.y + a3.y) * inv;
        o.z = (a0.z + a1.z + a2.z + a3.z) * inv;
        o.w = (a0.w + a1.w + a2.w + a3.w) * inv;
        *(float4*)(ssum + (size_t)n * LL + (threadIdx.x << 2)) = o;
    }
}

extern "C" void kernel_launch(void* const* d_in, const int* in_sizes, int n_in,
                              void* d_out, int out_size)
{
    const float* x     = (const float*)d_in[0];
    const int*   eidx  = (const int*)  d_in[1];
    const float* eattr = (const float*)d_in[2];
    const int*   batch = (const int*)  d_in[4];
    const float* W1  = (const float*)d_in[5];
    const float* b1  = (const float*)d_in[6];
    const float* g1  = (const float*)d_in[7];
    const float* be1 = (const float*)d_in[8];
    const float* W2  = (const float*)d_in[9];
    const float* b2  = (const float*)d_in[10];
    const float* g2  = (const float*)d_in[11];
    const float* be2 = (const float*)d_in[12];
    const float* W3  = (const float*)d_in[13];
    const float* b3  = (const float*)d_in[14];
    float* out = (float*)d_out;

    const int* erow = eidx;
    const int* ecol = eidx + NE;

    void *pY1, *pY2, *pXW, *pss, *pcnt, *poff, *pcur, *peid, *pW1e;
    void *ps1, *pq1, *psc1, *psh1, *ps2, *pq2, *psc2, *psh2;
    cudaGetSymbolAddress(&pY1,  g_Y1);
    cudaGetSymbolAddress(&pY2,  g_Y2);
    cudaGetSymbolAddress(&pXW,  g_XW);
    cudaGetSymbolAddress(&pss,  g_ssum);
    cudaGetSymbolAddress(&pcnt, g_cnt);
    cudaGetSymbolAddress(&poff, g_off);
    cudaGetSymbolAddress(&pcur, g_cur);
    cudaGetSymbolAddress(&peid, g_eid);
    cudaGetSymbolAddress(&pW1e, g_W1e);
    cudaGetSymbolAddress(&ps1,  g_sum1);   cudaGetSymbolAddress(&pq1,  g_sumsq1);
    cudaGetSymbolAddress(&psc1, g_scale1); cudaGetSymbolAddress(&psh1, g_shift1);
    cudaGetSymbolAddress(&ps2,  g_sum2);   cudaGetSymbolAddress(&pq2,  g_sumsq2);
    cudaGetSymbolAddress(&psc2, g_scale2); cudaGetSymbolAddress(&psh2, g_shift2);

    // persistent side stream + events (host objects; created once)
    static cudaStream_t s2 = nullptr;
    static cudaEvent_t ev1 = nullptr, ev2 = nullptr;
    if (!s2) {
        cudaStreamCreateWithFlags(&s2, cudaStreamNonBlocking);
        cudaEventCreateWithFlags(&ev1, cudaEventDisableTiming);
        cudaEventCreateWithFlags(&ev2, cudaEventDisableTiming);
    }

    cudaMemsetAsync(ps1,  0, LL  * sizeof(float), 0);
    cudaMemsetAsync(pq1,  0, LL  * sizeof(float), 0);
    cudaMemsetAsync(ps2,  0, DD2 * sizeof(float), 0);
    cudaMemsetAsync(pq2,  0, DD2 * sizeof(float), 0);
    cudaMemsetAsync(pcnt, 0, NN  * sizeof(int),   0);

    cudaFuncSetAttribute(edge_gemm, cudaFuncAttributeMaxDynamicSharedMemorySize, E_SMEM);

    // ---- fork: CSR build on side stream (depends only on ecol + cnt memset)
    cudaEventRecord(ev1, 0);
    cudaStreamWaitEvent(s2, ev1, 0);
    cnt_kernel<<<NE / 256, 256, 0, s2>>>(ecol, (int*)pcnt);
    scan_kernel<<<1, 1024, 0, s2>>>((int*)pcnt, (int*)poff, (int*)pcur);
    bucket_kernel<<<NE / 256, 256, 0, s2>>>(ecol, (int*)pcur, (int*)peid);
    cudaEventRecord(ev2, s2);

    // ---- main chain on stream 0
    prep_W1e<<<(LL * EFD + 255) / 256, 256>>>(W1, (uint32_t*)pW1e);

    gemm_tf32<3><<<dim3((NN + 127) / 128, LL / 64), 256>>>(
        NN, LL, KXW, W1, b1, nullptr, (__half*)pXW,
        x, batch, nullptr, nullptr, nullptr, nullptr, nullptr, nullptr, 0);

    edge_gemm<<<NE / 128, 256, E_SMEM>>>(eattr, erow, (const uint32_t*)pW1e,
                                         (const __half*)pXW, (__half*)pY1,
                                         (float*)ps1, (float*)pq1);
    finalize_kernel<<<2, 256>>>((float*)ps1, (float*)pq1, NE, LL, g1, be1,
                                (float*)psc1, (float*)psh1);

    // ---- join: gather needs CSR + Y1 + scale/shift
    cudaStreamWaitEvent(0, ev2, 0);
    gather_kernel<<<NN, 256>>>((const __half*)pY1, (int*)peid, (int*)poff,
                               (float*)psc1, (float*)psh1, (float*)pss);

    // node GEMM with fused BN2 stats
    gemm_tf32<1><<<dim3((NN + 127) / 128, (DD2 + 63) / 64), 256>>>(
        NN, DD2, DD2, W2, b2, (float*)pY2, nullptr,
        x, batch, (float*)pss, nullptr, nullptr, nullptr,
        (float*)ps2, (float*)pq2, 0);

    finalize_kernel<<<2, 256>>>((float*)ps2, (float*)pq2, NN, DD2, g2, be2,
                                (float*)psc2, (float*)psh2);

    gemm_tf32<2><<<dim3((NN + 127) / 128, NFD / 64), 256>>>(
        NN, NFD, DD2, W3, b3, out, nullptr,
        nullptr, batch, nullptr, (float*)pY2, (float*)psc2, (float*)psh2,
        nullptr, nullptr, 1);
}

// round 10
// speedup vs baseline: 4.1063x; 1.1182x over previous
#include <cuda_runtime.h>
#include <cuda_fp16.h>
#include <cstdint>
#include <math.h>

#define NN   50000      // nodes
#define NE   800000     // edges
#define NFD  128        // node feature size
#define EFD  64         // edge feature size
#define LL   256        // layer size (mlp1 out)
#define DD1  193        // mlp1 input dim
#define DD2  385        // mlp2 dim
#define KXW  129        // x + batch part of mlp1 K
#define BNEPS 1e-5f

// ---------------- scratch (static device globals) ---------------------------
__device__ __half   g_Y1[(size_t)NE * LL];     // edge MLP pre-BN output (fp16)
__device__ float    g_Y2[(size_t)NN * DD2];    // node MLP pre-BN output
__device__ __half   g_XW[(size_t)NN * LL];     // node part of edge MLP (fp16)
__device__ float    g_ssum[(size_t)NN * LL];   // aggregated means
__device__ __half   g_W1e[LL * EFD];           // W1[129:193]^T as fp16, [n][k]
__device__ int      g_cnt[NN];
__device__ int      g_off[NN + 1];
__device__ int      g_cur[NN];
__device__ int      g_eid[NE];
__device__ float    g_sum1[LL],  g_sumsq1[LL],  g_scale1[LL],  g_shift1[LL];
__device__ float    g_sum2[DD2], g_sumsq2[DD2], g_scale2[DD2], g_shift2[DD2];

// ---------------- fp16 mma helpers ------------------------------------------
__device__ __forceinline__ void mma_h(float* c, uint32_t a0, uint32_t a1,
                                      uint32_t a2, uint32_t a3,
                                      uint32_t b0, uint32_t b1) {
    asm volatile(
        "mma.sync.aligned.m16n8k16.row.col.f32.f16.f16.f32 "
        "{%0,%1,%2,%3},{%4,%5,%6,%7},{%8,%9},{%0,%1,%2,%3};"
        : "+f"(c[0]), "+f"(c[1]), "+f"(c[2]), "+f"(c[3])
        : "r"(a0), "r"(a1), "r"(a2), "r"(a3), "r"(b0), "r"(b1));
}
__device__ __forceinline__ uint32_t ldh2(const __half* p) {
    return *(const uint32_t*)p;
}
__device__ __forceinline__ uint32_t packh2(float a, float b) {
    __half2 h = __floats2half2_rn(a, b);
    return *(uint32_t*)&h;
}

// ---------------- prep: W1[129:193]^T -> fp16 [n][k] ------------------------
__global__ void prep_W1e(const float* __restrict__ W1, __half* __restrict__ W1e)
{
    int idx = blockIdx.x * 256 + threadIdx.x;    // LL*EFD = 16384
    if (idx >= LL * EFD) return;
    int n = idx >> 6, k = idx & 63;
    W1e[idx] = __float2half_rn(W1[(size_t)(KXW + k) * LL + n]);
}

// ---------------- edge GEMM (K=64, fp16 mma) + XW add + fused BN1 stats -----
// smem (bytes): As half[128][72]=18432, Bs half[64][72]=9216,
//               XWs float[128][68]=34816, rIdx 512, stats 2048
#define ESA    0
#define ESB    18432
#define ESXW   27648
#define ESRIDX 62464
#define ESSTAT 62976
#define E_SMEM 65024

__global__ void __launch_bounds__(256) edge_gemm(
    const float* __restrict__ eattr, const int* __restrict__ erow,
    const __half* __restrict__ W1e, const __half* __restrict__ XW,
    __half* __restrict__ Y1,
    float* __restrict__ gsum, float* __restrict__ gsq)
{
    extern __shared__ char smem[];
    __half (*As)[72]    = (__half(*)[72])(smem + ESA);
    __half (*Bs)[72]    = (__half(*)[72])(smem + ESB);
    float  (*XWs)[68]   = (float(*)[68]) (smem + ESXW);
    int*   rIdx = (int*)  (smem + ESRIDX);
    float* sSum = (float*)(smem + ESSTAT);
    float* sSq  = (float*)(smem + ESSTAT + 1024);

    const int tid  = threadIdx.x;
    const int wid  = tid >> 5, lane = tid & 31;
    const int gid  = lane >> 2, tg = lane & 3;
    const int m0   = blockIdx.x * 128;
    const int wm   = (wid & 3) * 32;
    const int wn   = (wid >> 2) * 32;

    // stage eattr tile [128 x 64] as fp16
    #pragma unroll
    for (int it = 0; it < 8; it++) {
        int idx = tid + it * 256;
        int row = idx >> 4, q = idx & 15;
        float4 v = *(const float4*)(eattr + (size_t)(m0 + row) * EFD + 4 * q);
        uint2 t; t.x = packh2(v.x, v.y); t.y = packh2(v.z, v.w);
        *(uint2*)&As[row][4 * q] = t;
    }
    if (tid < 128) rIdx[tid] = erow[m0 + tid];
    sSum[tid] = 0.f; sSq[tid] = 0.f;
    __syncthreads();

    for (int ct = 0; ct < 4; ct++) {
        const int n0 = ct * 64;
        // B tile [64 x 64] fp16: 8 chunks of 8 halves per row, uint4 = 8 halves
        #pragma unroll
        for (int it = 0; it < 2; it++) {
            int idx = tid + it * 256;      // 0..511
            int n = idx >> 3, q = idx & 7;
            uint4 t = *(const uint4*)(W1e + (size_t)(n0 + n) * EFD + 8 * q);
            *(uint4*)&Bs[n][8 * q] = t;    // byte off = n*144 + 16*q, 16B aligned
        }
        // XW tile [128 x 64] (fp16 -> fp32 in smem)
        #pragma unroll
        for (int it = 0; it < 8; it++) {
            int idx = tid + it * 256;
            int row = idx >> 4, q = idx & 15;
            uint2 raw = *(const uint2*)(XW + (size_t)rIdx[row] * LL + n0 + 4 * q);
            __half2* ph = (__half2*)&raw;
            float2 f0 = __half22float2(ph[0]);
            float2 f1 = __half22float2(ph[1]);
            *(float4*)&XWs[row][4 * q] = make_float4(f0.x, f0.y, f1.x, f1.y);
        }
        __syncthreads();

        float c[2][4][4];
        #pragma unroll
        for (int i = 0; i < 2; i++)
            #pragma unroll
            for (int j = 0; j < 4; j++)
                #pragma unroll
                for (int k = 0; k < 4; k++) c[i][j][k] = 0.f;

        #pragma unroll
        for (int ks = 0; ks < 64; ks += 16) {
            uint32_t a[2][4], b[4][2];
            #pragma unroll
            for (int mt = 0; mt < 2; mt++) {
                int r = wm + mt * 16;
                a[mt][0] = ldh2(&As[r + gid][ks + 2 * tg]);
                a[mt][1] = ldh2(&As[r + gid + 8][ks + 2 * tg]);
                a[mt][2] = ldh2(&As[r + gid][ks + 8 + 2 * tg]);
                a[mt][3] = ldh2(&As[r + gid + 8][ks + 8 + 2 * tg]);
            }
            #pragma unroll
            for (int nt = 0; nt < 4; nt++) {
                int cc = wn + nt * 8;
                b[nt][0] = ldh2(&Bs[cc + gid][ks + 2 * tg]);
                b[nt][1] = ldh2(&Bs[cc + gid][ks + 8 + 2 * tg]);
            }
            #pragma unroll
            for (int mt = 0; mt < 2; mt++)
                #pragma unroll
                for (int nt = 0; nt < 4; nt++)
                    mma_h(c[mt][nt], a[mt][0], a[mt][1], a[mt][2], a[mt][3],
                          b[nt][0], b[nt][1]);
        }

        float ls[8], lq[8];
        #pragma unroll
        for (int s = 0; s < 8; s++) { ls[s] = 0.f; lq[s] = 0.f; }
        #pragma unroll
        for (int mt = 0; mt < 2; mt++) {
            int r0 = wm + mt * 16 + gid;
            int r1 = r0 + 8;
            #pragma unroll
            for (int nt = 0; nt < 4; nt++) {
                int cb = wn + nt * 8 + 2 * tg;
                float v00 = c[mt][nt][0] + XWs[r0][cb];
                float v01 = c[mt][nt][1] + XWs[r0][cb + 1];
                float v10 = c[mt][nt][2] + XWs[r1][cb];
                float v11 = c[mt][nt][3] + XWs[r1][cb + 1];
                *(__half2*)(Y1 + (size_t)(m0 + r0) * LL + n0 + cb) = __floats2half2_rn(v00, v01);
                *(__half2*)(Y1 + (size_t)(m0 + r1) * LL + n0 + cb) = __floats2half2_rn(v10, v11);
                ls[nt * 2 + 0] += v00 + v10;  lq[nt * 2 + 0] += v00 * v00 + v10 * v10;
                ls[nt * 2 + 1] += v01 + v11;  lq[nt * 2 + 1] += v01 * v01 + v11 * v11;
            }
        }
        #pragma unroll
        for (int mask = 4; mask <= 16; mask <<= 1)
            #pragma unroll
            for (int s = 0; s < 8; s++) {
                ls[s] += __shfl_xor_sync(0xffffffffu, ls[s], mask);
                lq[s] += __shfl_xor_sync(0xffffffffu, lq[s], mask);
            }
        if (gid == 0) {
            #pragma unroll
            for (int nt = 0; nt < 4; nt++)
                #pragma unroll
                for (int h = 0; h < 2; h++) {
                    int col = n0 + wn + nt * 8 + 2 * tg + h;
                    atomicAdd(&sSum[col], ls[nt * 2 + h]);
                    atomicAdd(&sSq[col],  lq[nt * 2 + h]);
                }
        }
        __syncthreads();
    }
    atomicAdd(&gsum[tid], sSum[tid]);
    atomicAdd(&gsq[tid],  sSq[tid]);
}

// ---------------- generic fp16-mma GEMM (modes 1,2,3) -----------------------
//   MODE 1: node rows  = [x[m], batch[m], agg[m]]  + fused BN2 stats
//   MODE 2: relu(bn(Y2[m]))  (output)
//   MODE 3: xw rows    = [x[m], batch[m]]          (XW, fp16 output)
template<int MODE>
__global__ void __launch_bounds__(256) gemm_f16(int M, int Nc, int K,
    const float* __restrict__ B, const float* __restrict__ bias,
    float* __restrict__ C, __half* __restrict__ Ch,
    const float* __restrict__ x, const int* __restrict__ batch,
    const float* __restrict__ agg,
    const float* __restrict__ Y2,
    const float* __restrict__ scale, const float* __restrict__ shift,
    float* __restrict__ gsum, float* __restrict__ gsq,
    int relu_out)
{
    __shared__ __half As[128][24];
    __shared__ __half Bs[64][24];

    const int tid = threadIdx.x;
    const int wid = tid >> 5, lane = tid & 31;
    const int gid = lane >> 2, tg = lane & 3;
    const int m0  = blockIdx.x * 128, n0 = blockIdx.y * 64;
    const int wm  = (wid & 3) * 32;
    const int wn  = (wid >> 2) * 32;

    float c[2][4][4];
    #pragma unroll
    for (int i = 0; i < 2; i++)
        #pragma unroll
        for (int j = 0; j < 4; j++)
            #pragma unroll
            for (int k = 0; k < 4; k++) c[i][j][k] = 0.f;

    const int kk = tid & 15;
    const int mb = tid >> 4;
    const int bn = tid & 63;
    const int bk = tid >> 6;

    for (int k0 = 0; k0 < K; k0 += 16) {
        int gk = k0 + kk;
        #pragma unroll
        for (int i = 0; i < 8; i++) {
            int mm = mb + i * 16;
            int gm = m0 + mm;
            float v = 0.f;
            if (gm < M && gk < K) {
                if (MODE == 1) {
                    if (gk < NFD)       v = x[(size_t)gm * NFD + gk];
                    else if (gk == NFD) v = (float)batch[gm];
                    else                v = agg[(size_t)gm * LL + (gk - NFD - 1)];
                } else if (MODE == 3) {
                    if (gk < NFD)       v = x[(size_t)gm * NFD + gk];
                    else                v = (float)batch[gm];
                } else {
                    float y = Y2[(size_t)gm * DD2 + gk];
                    v = fmaxf(fmaf(y, scale[gk], shift[gk]), 0.f);
                }
            }
            As[mm][kk] = __float2half_rn(v);
        }
        #pragma unroll
        for (int i = 0; i < 4; i++) {
            int k = bk + i * 4;
            int gkb = k0 + k;
            int gn = n0 + bn;
            float v = (gkb < K && gn < Nc) ? B[(size_t)gkb * Nc + gn] : 0.f;
            Bs[bn][k] = __float2half_rn(v);
        }
        __syncthreads();
        {
            uint32_t a[2][4], b[4][2];
            #pragma unroll
            for (int mt = 0; mt < 2; mt++) {
                int rr = wm + mt * 16;
                a[mt][0] = ldh2(&As[rr + gid][2 * tg]);
                a[mt][1] = ldh2(&As[rr + gid + 8][2 * tg]);
                a[mt][2] = ldh2(&As[rr + gid][8 + 2 * tg]);
                a[mt][3] = ldh2(&As[rr + gid + 8][8 + 2 * tg]);
            }
            #pragma unroll
            for (int nt = 0; nt < 4; nt++) {
                int cc = wn + nt * 8;
                b[nt][0] = ldh2(&Bs[cc + gid][2 * tg]);
                b[nt][1] = ldh2(&Bs[cc + gid][8 + 2 * tg]);
            }
            #pragma unroll
            for (int mt = 0; mt < 2; mt++)
                #pragma unroll
                for (int nt = 0; nt < 4; nt++)
                    mma_h(c[mt][nt], a[mt][0], a[mt][1], a[mt][2], a[mt][3],
                          b[nt][0], b[nt][1]);
        }
        __syncthreads();
    }

    float ls[8], lq[8];
    if (MODE == 1) {
        #pragma unroll
        for (int s = 0; s < 8; s++) { ls[s] = 0.f; lq[s] = 0.f; }
    }
    #pragma unroll
    for (int mt = 0; mt < 2; mt++) {
        int r0 = m0 + wm + mt * 16 + gid;
        int r1 = r0 + 8;
        #pragma unroll
        for (int nt = 0; nt < 4; nt++) {
            int cb = wn + nt * 8 + 2 * tg;
            if (MODE == 3) {
                float b0 = bias[n0 + cb], b1 = bias[n0 + cb + 1];
                if (r0 < M)
                    *(__half2*)(Ch + (size_t)r0 * Nc + n0 + cb) =
                        __floats2half2_rn(c[mt][nt][0] + b0, c[mt][nt][1] + b1);
                if (r1 < M)
                    *(__half2*)(Ch + (size_t)r1 * Nc + n0 + cb) =
                        __floats2half2_rn(c[mt][nt][2] + b0, c[mt][nt][3] + b1);
            } else {
                #pragma unroll
                for (int h = 0; h < 2; h++) {
                    int col = n0 + cb + h;
                    if (col >= Nc) continue;
                    float bb = bias[col];
                    if (r0 < M) {
                        float v = c[mt][nt][h] + bb;
                        if (relu_out) v = fmaxf(v, 0.f);
                        C[(size_t)r0 * Nc + col] = v;
                        if (MODE == 1) { ls[nt * 2 + h] += v; lq[nt * 2 + h] += v * v; }
                    }
                    if (r1 < M) {
                        float v = c[mt][nt][2 + h] + bb;
                        if (relu_out) v = fmaxf(v, 0.f);
                        C[(size_t)r1 * Nc + col] = v;
                        if (MODE == 1) { ls[nt * 2 + h] += v; lq[nt * 2 + h] += v * v; }
                    }
                }
            }
        }
    }
    if (MODE == 1) {
        #pragma unroll
        for (int mask = 4; mask <= 16; mask <<= 1)
            #pragma unroll
            for (int s = 0; s < 8; s++) {
                ls[s] += __shfl_xor_sync(0xffffffffu, ls[s], mask);
                lq[s] += __shfl_xor_sync(0xffffffffu, lq[s], mask);
            }
        if (gid == 0) {
            #pragma unroll
            for (int nt = 0; nt < 4; nt++)
                #pragma unroll
                for (int h = 0; h < 2; h++) {
                    int col = n0 + wn + nt * 8 + 2 * tg + h;
                    if (col < Nc) {
                        atomicAdd(&gsum[col], ls[nt * 2 + h]);
                        atomicAdd(&gsq[col],  lq[nt * 2 + h]);
                    }
                }
        }
    }
}

// ---------------- BN finalize / CSR / gather --------------------------------
__global__ void finalize_kernel(const float* __restrict__ sum, const float* __restrict__ sumsq,
                                int M, int C,
                                const float* __restrict__ gamma, const float* __restrict__ beta,
                                float* __restrict__ scale, float* __restrict__ shift)
{
    int c = blockIdx.x * blockDim.x + threadIdx.x;
    if (c < C) {
        float mu  = sum[c] / (float)M;
        float var = sumsq[c] / (float)M - mu * mu;
        float sc  = rsqrtf(var + BNEPS) * gamma[c];
        scale[c] = sc;
        shift[c] = beta[c] - mu * sc;
    }
}

__global__ void cnt_kernel(const int* __restrict__ col, int* __restrict__ cnt)
{
    int e = blockIdx.x * blockDim.x + threadIdx.x;
    if (e < NE) atomicAdd(&cnt[col[e]], 1);
}

__global__ void scan_kernel(const int* __restrict__ cnt,
                            int* __restrict__ off, int* __restrict__ cur)
{
    __shared__ int warpsum[32];
    __shared__ int base_s;
    int tid = threadIdx.x, lane = tid & 31, w = tid >> 5;
    if (tid == 0) base_s = 0;
    __syncthreads();
    for (int c0 = 0; c0 < NN; c0 += 1024) {
        int i = c0 + tid;
        int v = (i < NN) ? cnt[i] : 0;
        int inc = v;
        #pragma unroll
        for (int s = 1; s < 32; s <<= 1) {
            int t = __shfl_up_sync(0xffffffffu, inc, s);
            if (lane >= s) inc += t;
        }
        if (lane == 31) warpsum[w] = inc;
        __syncthreads();
        if (w == 0) {
            int ws = warpsum[lane];
            #pragma unroll
            for (int s = 1; s < 32; s <<= 1) {
                int t = __shfl_up_sync(0xffffffffu, ws, s);
                if (lane >= s) ws += t;
            }
            warpsum[lane] = ws;
        }
        __syncthreads();
        int base = base_s;
        int wexc = (w > 0) ? warpsum[w - 1] : 0;
        int excl = base + wexc + inc - v;
        if (i < NN) { off[i] = excl; cur[i] = excl; }
        int total = warpsum[31];
        __syncthreads();
        if (tid == 0) base_s = base + total;
        __syncthreads();
    }
    if (threadIdx.x == 0) off[NN] = base_s;
}

__global__ void bucket_kernel(const int* __restrict__ col,
                              int* __restrict__ cur, int* __restrict__ eid)
{
    int e = blockIdx.x * blockDim.x + threadIdx.x;
    if (e < NE) {
        int pos = atomicAdd(&cur[col[e]], 1);
        eid[pos] = e;
    }
}

// per-node gather-sum of relu(bn(Y1)) rows (fp16 Y1), then mean
__global__ void __launch_bounds__(256) gather_kernel(
    const __half* __restrict__ Y1,
    const int* __restrict__ eid, const int* __restrict__ off,
    const float* __restrict__ scale, const float* __restrict__ shift,
    float* __restrict__ ssum)
{
    __shared__ float4 part[4][64];
    const int n   = blockIdx.x;
    const int sub = threadIdx.x >> 6;
    const int cgi = threadIdx.x & 63;
    const int cg  = cgi << 2;
    const int s = off[n], e = off[n + 1];

    float4 sc = *(const float4*)(scale + cg);
    float4 sh = *(const float4*)(shift + cg);
    float4 acc = make_float4(0.f, 0.f, 0.f, 0.f);

    for (int j = s + sub; j < e; j += 4) {
        int ej = eid[j];
        uint2 raw = *(const uint2*)(Y1 + (size_t)ej * LL + cg);
        __half2* ph = (__half2*)&raw;
        float2 y0 = __half22float2(ph[0]);
        float2 y1 = __half22float2(ph[1]);
        acc.x += fmaxf(fmaf(y0.x, sc.x, sh.x), 0.f);
        acc.y += fmaxf(fmaf(y0.y, sc.y, sh.y), 0.f);
        acc.z += fmaxf(fmaf(y1.x, sc.z, sh.z), 0.f);
        acc.w += fmaxf(fmaf(y1.y, sc.w, sh.w), 0.f);
    }
    part[sub][cgi] = acc;
    __syncthreads();
    if (threadIdx.x < 64) {
        float4 a0 = part[0][threadIdx.x], a1 = part[1][threadIdx.x];
        float4 a2 = part[2][threadIdx.x], a3 = part[3][threadIdx.x];
        float inv = 1.f / (float)max(e - s, 1);
        float4 o;
        o.x = (a0.x + a1.x + a2.x + a3.x) * inv;
        o.y = (a0.y + a1.y + a2.y + a3.y) * inv;
        o.z = (a0.z + a1.z + a2.z + a3.z) * inv;
        o.w = (a0.w + a1.w + a2.w + a3.w) * inv;
        *(float4*)(ssum + (size_t)n * LL + (threadIdx.x << 2)) = o;
    }
}

extern "C" void kernel_launch(void* const* d_in, const int* in_sizes, int n_in,
                              void* d_out, int out_size)
{
    const float* x     = (const float*)d_in[0];
    const int*   eidx  = (const int*)  d_in[1];
    const float* eattr = (const float*)d_in[2];
    const int*   batch = (const int*)  d_in[4];
    const float* W1  = (const float*)d_in[5];
    const float* b1  = (const float*)d_in[6];
    const float* g1  = (const float*)d_in[7];
    const float* be1 = (const float*)d_in[8];
    const float* W2  = (const float*)d_in[9];
    const float* b2  = (const float*)d_in[10];
    const float* g2  = (const float*)d_in[11];
    const float* be2 = (const float*)d_in[12];
    const float* W3  = (const float*)d_in[13];
    const float* b3  = (const float*)d_in[14];
    float* out = (float*)d_out;

    const int* erow = eidx;
    const int* ecol = eidx + NE;

    void *pY1, *pY2, *pXW, *pss, *pcnt, *poff, *pcur, *peid, *pW1e;
    void *ps1, *pq1, *psc1, *psh1, *ps2, *pq2, *psc2, *psh2;
    cudaGetSymbolAddress(&pY1,  g_Y1);
    cudaGetSymbolAddress(&pY2,  g_Y2);
    cudaGetSymbolAddress(&pXW,  g_XW);
    cudaGetSymbolAddress(&pss,  g_ssum);
    cudaGetSymbolAddress(&pcnt, g_cnt);
    cudaGetSymbolAddress(&poff, g_off);
    cudaGetSymbolAddress(&pcur, g_cur);
    cudaGetSymbolAddress(&peid, g_eid);
    cudaGetSymbolAddress(&pW1e, g_W1e);
    cudaGetSymbolAddress(&ps1,  g_sum1);   cudaGetSymbolAddress(&pq1,  g_sumsq1);
    cudaGetSymbolAddress(&psc1, g_scale1); cudaGetSymbolAddress(&psh1, g_shift1);
    cudaGetSymbolAddress(&ps2,  g_sum2);   cudaGetSymbolAddress(&pq2,  g_sumsq2);
    cudaGetSymbolAddress(&psc2, g_scale2); cudaGetSymbolAddress(&psh2, g_shift2);

    static cudaStream_t s2 = nullptr;
    static cudaEvent_t ev1 = nullptr, ev2 = nullptr;
    if (!s2) {
        cudaStreamCreateWithFlags(&s2, cudaStreamNonBlocking);
        cudaEventCreateWithFlags(&ev1, cudaEventDisableTiming);
        cudaEventCreateWithFlags(&ev2, cudaEventDisableTiming);
    }

    cudaMemsetAsync(ps1,  0, LL  * sizeof(float), 0);
    cudaMemsetAsync(pq1,  0, LL  * sizeof(float), 0);
    cudaMemsetAsync(ps2,  0, DD2 * sizeof(float), 0);
    cudaMemsetAsync(pq2,  0, DD2 * sizeof(float), 0);
    cudaMemsetAsync(pcnt, 0, NN  * sizeof(int),   0);

    cudaFuncSetAttribute(edge_gemm, cudaFuncAttributeMaxDynamicSharedMemorySize, E_SMEM);

    // ---- fork: CSR build on side stream
    cudaEventRecord(ev1, 0);
    cudaStreamWaitEvent(s2, ev1, 0);
    cnt_kernel<<<NE / 256, 256, 0, s2>>>(ecol, (int*)pcnt);
    scan_kernel<<<1, 1024, 0, s2>>>((int*)pcnt, (int*)poff, (int*)pcur);
    bucket_kernel<<<NE / 256, 256, 0, s2>>>(ecol, (int*)pcur, (int*)peid);
    cudaEventRecord(ev2, s2);

    // ---- main chain
    prep_W1e<<<(LL * EFD + 255) / 256, 256>>>(W1, (__half*)pW1e);

    gemm_f16<3><<<dim3((NN + 127) / 128, LL / 64), 256>>>(
        NN, LL, KXW, W1, b1, nullptr, (__half*)pXW,
        x, batch, nullptr, nullptr, nullptr, nullptr, nullptr, nullptr, 0);

    edge_gemm<<<NE / 128, 256, E_SMEM>>>(eattr, erow, (const __half*)pW1e,
                                         (const __half*)pXW, (__half*)pY1,
                                         (float*)ps1, (float*)pq1);
    finalize_kernel<<<2, 256>>>((float*)ps1, (float*)pq1, NE, LL, g1, be1,
                                (float*)psc1, (float*)psh1);

    // ---- join: gather needs CSR + Y1 + scale/shift
    cudaStreamWaitEvent(0, ev2, 0);
    gather_kernel<<<NN, 256>>>((const __half*)pY1, (int*)peid, (int*)poff,
                               (float*)psc1, (float*)psh1, (float*)pss);

    gemm_f16<1><<<dim3((NN + 127) / 128, (DD2 + 63) / 64), 256>>>(
        NN, DD2, DD2, W2, b2, (float*)pY2, nullptr,
        x, batch, (float*)pss, nullptr, nullptr, nullptr,
        (float*)ps2, (float*)pq2, 0);

    finalize_kernel<<<2, 256>>>((float*)ps2, (float*)pq2, NN, DD2, g2, be2,
                                (float*)psc2, (float*)psh2);

    gemm_f16<2><<<dim3((NN + 127) / 128, NFD / 64), 256>>>(
        NN, NFD, DD2, W3, b3, out, nullptr,
        nullptr, batch, nullptr, (float*)pY2, (float*)psc2, (float*)psh2,
        nullptr, nullptr, 1);
}